// round 1
// baseline (speedup 1.0000x reference)
#include <cuda_runtime.h>
#include <cstdint>
#include <math.h>

#define BATCH 8
#define SEQ   2048
#define DIM   1024
#define HID   4096
#define ROWS  (BATCH*SEQ)   /* 16384 */

// ---------------- scratch (allocation-free: __device__ globals) ----------------
static __device__ float g_xn  [(size_t)ROWS*DIM];
static __device__ float g_q   [(size_t)ROWS*DIM];
static __device__ float g_k   [(size_t)ROWS*DIM];
static __device__ float g_v   [(size_t)ROWS*DIM];
static __device__ float g_attn[(size_t)ROWS*DIM];
static __device__ float g_xmid[(size_t)ROWS*DIM];
static __device__ float g_h1  [(size_t)ROWS*HID];
static __device__ float g_sc  [(size_t)BATCH*SEQ*SEQ];

// ---------------- helpers ----------------
__device__ __forceinline__ uint32_t f2tf32(float f) {
    uint32_t r;
    asm("cvt.rna.tf32.f32 %0, %1;" : "=r"(r) : "f"(f));
    return r;
}

__device__ __forceinline__ float gelu_exact(float x) {
    return 0.5f * x * (1.0f + erff(x * 0.70710678118654752440f));
}

__device__ __forceinline__ void mma_tf32(float d[4], const uint32_t a[4], const uint32_t b[2]) {
    asm volatile(
        "mma.sync.aligned.m16n8k8.row.col.f32.tf32.tf32.f32 "
        "{%0,%1,%2,%3}, {%4,%5,%6,%7}, {%8,%9}, {%0,%1,%2,%3};\n"
        : "+f"(d[0]), "+f"(d[1]), "+f"(d[2]), "+f"(d[3])
        : "r"(a[0]), "r"(a[1]), "r"(a[2]), "r"(a[3]), "r"(b[0]), "r"(b[1]));
}

// ---------------- GEMM ----------------
// C[M,N] = A[M,K] @ B + epilogue.
//   BT=false : B is [K,N] row-major (NN)
//   BT=true  : B is [N,K] row-major (NT, i.e. C = A @ B^T)
//   CAUSAL   : square tile grid; CTA exits if its N-tile > M-tile (upper triangle)
//   PVT      : truncate K loop at end of this M-tile (P@V causal structure)
// EPI: 0=store, 1=+bias, 2=+bias+res, 3=gelu(.+bias)
#define EPI_STORE    0
#define EPI_BIAS     1
#define EPI_BIAS_RES 2
#define EPI_GELU     3

template<int EPI, bool BT, bool CAUSAL, bool PVT>
__global__ void __launch_bounds__(256, 1)
gemm_k(const float* __restrict__ A, const float* __restrict__ B,
       const float* __restrict__ bias, const float* __restrict__ res,
       float* __restrict__ C, int M, int N, int K,
       long long aB, long long bB, long long cB)
{
    const int bn = blockIdx.x, bm = blockIdx.y, bz = blockIdx.z;
    if (CAUSAL && bn > bm) return;
    A += (long long)bz * aB;
    B += (long long)bz * bB;
    C += (long long)bz * cB;

    __shared__ uint32_t As[128][36];   // stride 36: conflict-free frag loads
    __shared__ uint32_t Bs[32][136];   // stride 136: conflict-free frag loads

    const int tid  = threadIdx.x;
    const int lane = tid & 31;
    const int warp = tid >> 5;
    const int wm = (warp >> 1) * 32;   // 4 warps along M
    const int wn = (warp & 1) * 64;    // 2 warps along N
    const int g  = lane >> 2;          // groupID
    const int tg = lane & 3;           // thread-in-group
    const int m0 = bm * 128, n0 = bn * 128;

    int ktiles = K / 32;
    if (PVT) { int kt2 = (bm + 1) * 4; if (kt2 < ktiles) ktiles = kt2; }

    float acc[2][8][4];
#pragma unroll
    for (int i = 0; i < 2; i++)
#pragma unroll
        for (int j = 0; j < 8; j++)
#pragma unroll
            for (int r = 0; r < 4; r++) acc[i][j][r] = 0.0f;

    float4 ra[4], rb[4];

    auto loadA = [&](int kt) {
        const int col = (tid & 7) * 4;
#pragma unroll
        for (int i = 0; i < 4; i++) {
            const int row = (tid >> 3) + i * 32;
            ra[i] = *(const float4*)(A + (size_t)(m0 + row) * K + kt * 32 + col);
        }
    };
    auto loadB = [&](int kt) {
        if (!BT) {
            const int nc = (tid & 31) * 4;
#pragma unroll
            for (int i = 0; i < 4; i++) {
                const int kr = (tid >> 5) + i * 8;
                rb[i] = *(const float4*)(B + (size_t)(kt * 32 + kr) * N + n0 + nc);
            }
        } else {
            const int kv = (tid & 7) * 4;
#pragma unroll
            for (int i = 0; i < 4; i++) {
                const int n = (tid >> 3) + i * 32;
                rb[i] = *(const float4*)(B + (size_t)(n0 + n) * K + kt * 32 + kv);
            }
        }
    };
    auto storeA = [&]() {
        const int col = (tid & 7) * 4;
#pragma unroll
        for (int i = 0; i < 4; i++) {
            const int row = (tid >> 3) + i * 32;
            uint4 v;
            v.x = f2tf32(ra[i].x); v.y = f2tf32(ra[i].y);
            v.z = f2tf32(ra[i].z); v.w = f2tf32(ra[i].w);
            *(uint4*)&As[row][col] = v;
        }
    };
    auto storeB = [&]() {
        if (!BT) {
            const int nc = (tid & 31) * 4;
#pragma unroll
            for (int i = 0; i < 4; i++) {
                const int kr = (tid >> 5) + i * 8;
                uint4 v;
                v.x = f2tf32(rb[i].x); v.y = f2tf32(rb[i].y);
                v.z = f2tf32(rb[i].z); v.w = f2tf32(rb[i].w);
                *(uint4*)&Bs[kr][nc] = v;
            }
        } else {
            const int kv = (tid & 7) * 4;
#pragma unroll
            for (int i = 0; i < 4; i++) {
                const int n = (tid >> 3) + i * 32;
                Bs[kv + 0][n] = f2tf32(rb[i].x);
                Bs[kv + 1][n] = f2tf32(rb[i].y);
                Bs[kv + 2][n] = f2tf32(rb[i].z);
                Bs[kv + 3][n] = f2tf32(rb[i].w);
            }
        }
    };

    loadA(0); loadB(0);
    storeA(); storeB();
    __syncthreads();

    for (int kt = 0; kt < ktiles; kt++) {
        const bool more = (kt + 1) < ktiles;
        if (more) { loadA(kt + 1); loadB(kt + 1); }

#pragma unroll
        for (int ks = 0; ks < 4; ks++) {
            const int k0 = ks * 8;
            uint32_t af[2][4];
#pragma unroll
            for (int mi = 0; mi < 2; mi++) {
                const int r = wm + mi * 16 + g;
                af[mi][0] = As[r    ][k0 + tg];
                af[mi][1] = As[r + 8][k0 + tg];
                af[mi][2] = As[r    ][k0 + tg + 4];
                af[mi][3] = As[r + 8][k0 + tg + 4];
            }
            uint32_t bf[8][2];
#pragma unroll
            for (int ni = 0; ni < 8; ni++) {
                const int c = wn + ni * 8 + g;
                bf[ni][0] = Bs[k0 + tg    ][c];
                bf[ni][1] = Bs[k0 + tg + 4][c];
            }
#pragma unroll
            for (int mi = 0; mi < 2; mi++)
#pragma unroll
                for (int ni = 0; ni < 8; ni++)
                    mma_tf32(acc[mi][ni], af[mi], bf[ni]);
        }
        __syncthreads();
        if (more) { storeA(); storeB(); __syncthreads(); }
    }

    // epilogue
#pragma unroll
    for (int mi = 0; mi < 2; mi++) {
#pragma unroll
        for (int ni = 0; ni < 8; ni++) {
            const int r = m0 + wm + mi * 16 + g;
            const int c = n0 + wn + ni * 8 + tg * 2;
#pragma unroll
            for (int h = 0; h < 2; h++) {
                const int rr = r + h * 8;
                float v0 = acc[mi][ni][h * 2 + 0];
                float v1 = acc[mi][ni][h * 2 + 1];
                if (EPI == EPI_BIAS || EPI == EPI_BIAS_RES || EPI == EPI_GELU) {
                    v0 += bias[c]; v1 += bias[c + 1];
                }
                if (EPI == EPI_BIAS_RES) {
                    v0 += res[(size_t)rr * N + c];
                    v1 += res[(size_t)rr * N + c + 1];
                }
                if (EPI == EPI_GELU) { v0 = gelu_exact(v0); v1 = gelu_exact(v1); }
                *(float2*)&C[(size_t)rr * N + c] = make_float2(v0, v1);
            }
        }
    }
}

// ---------------- RMSNorm ----------------
__global__ void __launch_bounds__(256, 1)
rmsnorm_k(const float* __restrict__ x, const float* __restrict__ w, float* __restrict__ o)
{
    __shared__ float red[8];
    __shared__ float bc;
    const int row = blockIdx.x;
    const size_t base = (size_t)row * DIM;
    const int tid = threadIdx.x, lane = tid & 31, warp = tid >> 5;

    float4 xv = ((const float4*)(x + base))[tid];
    float ss = xv.x * xv.x + xv.y * xv.y + xv.z * xv.z + xv.w * xv.w;
#pragma unroll
    for (int off = 16; off; off >>= 1) ss += __shfl_xor_sync(0xffffffffu, ss, off);
    if (lane == 0) red[warp] = ss;
    __syncthreads();
    if (tid == 0) {
        float t = 0.0f;
#pragma unroll
        for (int i = 0; i < 8; i++) t += red[i];
        bc = rsqrtf(t * (1.0f / DIM) + 1e-6f);
    }
    __syncthreads();
    const float inv = bc;
    float4 wv = ((const float4*)w)[tid];
    float4 ov;
    ov.x = xv.x * inv * wv.x; ov.y = xv.y * inv * wv.y;
    ov.z = xv.z * inv * wv.z; ov.w = xv.w * inv * wv.w;
    ((float4*)(o + base))[tid] = ov;
}

// ---------------- causal softmax (in place, with zero-fill to tile edge) ----------------
__global__ void __launch_bounds__(256, 1)
softmax_k(float* __restrict__ s)
{
    __shared__ float red[8];
    __shared__ float bc;
    const int t = blockIdx.x, b = blockIdx.y;
    float* row = s + ((size_t)b * SEQ + (size_t)t) * SEQ;
    const int L = t + 1;
    const int tid = threadIdx.x, lane = tid & 31, warp = tid >> 5;
    const float scale = 0.03125f;  // 1/sqrt(1024)

    float m = -3.4e38f;
    for (int j = tid; j < L; j += 256) m = fmaxf(m, row[j]);
#pragma unroll
    for (int off = 16; off; off >>= 1) m = fmaxf(m, __shfl_xor_sync(0xffffffffu, m, off));
    if (lane == 0) red[warp] = m;
    __syncthreads();
    if (tid == 0) {
        float mm = red[0];
#pragma unroll
        for (int i = 1; i < 8; i++) mm = fmaxf(mm, red[i]);
        bc = mm;
    }
    __syncthreads();
    const float mm = bc;
    __syncthreads();

    float sum = 0.0f;
    for (int j = tid; j < L; j += 256) {
        float e = expf((row[j] - mm) * scale);
        row[j] = e;
        sum += e;
    }
#pragma unroll
    for (int off = 16; off; off >>= 1) sum += __shfl_xor_sync(0xffffffffu, sum, off);
    if (lane == 0) red[warp] = sum;
    __syncthreads();
    if (tid == 0) {
        float ss = 0.0f;
#pragma unroll
        for (int i = 0; i < 8; i++) ss += red[i];
        bc = 1.0f / ss;
    }
    __syncthreads();
    const float inv = bc;
    for (int j = tid; j < L; j += 256) row[j] *= inv;

    // zero-fill masked region up to this row's 128-tile edge (P@V reads it)
    const int jend = ((t >> 7) + 1) << 7;
    for (int j = L + tid; j < jend; j += 256) row[j] = 0.0f;
}

// ---------------- launch ----------------
extern "C" void kernel_launch(void* const* d_in, const int* in_sizes, int n_in,
                              void* d_out, int out_size)
{
    (void)in_sizes; (void)n_in; (void)out_size;
    const float* x   = (const float*)d_in[0];
    const float* anw = (const float*)d_in[1];
    const float* mnw = (const float*)d_in[2];
    const float* wq  = (const float*)d_in[3];
    const float* bq  = (const float*)d_in[4];
    const float* wk  = (const float*)d_in[5];
    const float* bk  = (const float*)d_in[6];
    const float* wv  = (const float*)d_in[7];
    const float* bv  = (const float*)d_in[8];
    const float* wo  = (const float*)d_in[9];
    const float* bo  = (const float*)d_in[10];
    const float* w1  = (const float*)d_in[11];
    const float* b1  = (const float*)d_in[12];
    const float* w2  = (const float*)d_in[13];
    const float* b2  = (const float*)d_in[14];
    float* out = (float*)d_out;

    float *xn, *q, *k, *v, *attn, *xmid, *h1, *sc;
    cudaGetSymbolAddress((void**)&xn,   g_xn);
    cudaGetSymbolAddress((void**)&q,    g_q);
    cudaGetSymbolAddress((void**)&k,    g_k);
    cudaGetSymbolAddress((void**)&v,    g_v);
    cudaGetSymbolAddress((void**)&attn, g_attn);
    cudaGetSymbolAddress((void**)&xmid, g_xmid);
    cudaGetSymbolAddress((void**)&h1,   g_h1);
    cudaGetSymbolAddress((void**)&sc,   g_sc);

    const long long qkB = (long long)SEQ * DIM;
    const long long scB = (long long)SEQ * SEQ;

    // 1) xn = rmsnorm(x) * attn_norm_w
    rmsnorm_k<<<ROWS, 256>>>(x, anw, xn);

    // 2) Q, K, V = xn @ W + b
    gemm_k<EPI_BIAS, false, false, false><<<dim3(DIM/128, ROWS/128, 1), 256>>>(
        xn, wq, bq, nullptr, q, ROWS, DIM, DIM, 0, 0, 0);
    gemm_k<EPI_BIAS, false, false, false><<<dim3(DIM/128, ROWS/128, 1), 256>>>(
        xn, wk, bk, nullptr, k, ROWS, DIM, DIM, 0, 0, 0);
    gemm_k<EPI_BIAS, false, false, false><<<dim3(DIM/128, ROWS/128, 1), 256>>>(
        xn, wv, bv, nullptr, v, ROWS, DIM, DIM, 0, 0, 0);

    // 3) scores = Q @ K^T (per batch, causal block-skip)
    gemm_k<EPI_STORE, true, true, false><<<dim3(SEQ/128, SEQ/128, BATCH), 256>>>(
        q, k, nullptr, nullptr, sc, SEQ, SEQ, DIM, qkB, qkB, scB);

    // 4) causal softmax (scale 1/32 inside)
    softmax_k<<<dim3(SEQ, BATCH), 256>>>(sc);

    // 5) attn = P @ V (K loop truncated at causal tile edge)
    gemm_k<EPI_STORE, false, false, true><<<dim3(DIM/128, SEQ/128, BATCH), 256>>>(
        sc, v, nullptr, nullptr, attn, SEQ, DIM, SEQ, scB, qkB, qkB);

    // 6) xmid = x + attn @ wo + bo
    gemm_k<EPI_BIAS_RES, false, false, false><<<dim3(DIM/128, ROWS/128, 1), 256>>>(
        attn, wo, bo, x, xmid, ROWS, DIM, DIM, 0, 0, 0);

    // 7) h = rmsnorm(xmid) * mlp_norm_w
    rmsnorm_k<<<ROWS, 256>>>(xmid, mnw, xn);

    // 8) h1 = gelu(h @ w1 + b1)
    gemm_k<EPI_GELU, false, false, false><<<dim3(HID/128, ROWS/128, 1), 256>>>(
        xn, w1, b1, nullptr, h1, ROWS, HID, DIM, 0, 0, 0);

    // 9) out = xmid + h1 @ w2 + b2
    gemm_k<EPI_BIAS_RES, false, false, false><<<dim3(DIM/128, ROWS/128, 1), 256>>>(
        h1, w2, b2, xmid, out, ROWS, DIM, HID, 0, 0, 0);
}

// round 2
// speedup vs baseline: 1.2230x; 1.2230x over previous
#include <cuda_runtime.h>
#include <cstdint>
#include <math.h>

#define BATCH 8
#define SEQ   2048
#define DIM   1024
#define HID   4096
#define ROWS  (BATCH*SEQ)   /* 16384 */

// GEMM tiling
#define MT 256
#define NT 128
#define KT 32
#define STAGES 3
#define ASTRIDE 36            /* floats per A-row in smem  (256 rows) */
#define BSTRIDE_NN 136        /* floats per B-row (k-major, 32 rows)  */
#define BSTRIDE_NT 36         /* floats per B-row (n-major, 128 rows) */
#define A_STAGE (MT*ASTRIDE)            /* 9216 floats */
#define B_STAGE (NT*BSTRIDE_NT)         /* 4608 floats (>= 32*136=4352) */
#define STAGE_F (A_STAGE + B_STAGE)     /* 13824 floats */
#define SMEM_BYTES (STAGES*STAGE_F*4)   /* 165888 bytes */

// ---------------- scratch (allocation-free: __device__ globals) ----------------
static __device__ float g_xn  [(size_t)ROWS*DIM];
static __device__ float g_q   [(size_t)ROWS*DIM];
static __device__ float g_k   [(size_t)ROWS*DIM];
static __device__ float g_v   [(size_t)ROWS*DIM];
static __device__ float g_attn[(size_t)ROWS*DIM];
static __device__ float g_xmid[(size_t)ROWS*DIM];
static __device__ float g_h1  [(size_t)ROWS*HID];
static __device__ float g_sc  [(size_t)BATCH*SEQ*SEQ];

// ---------------- helpers ----------------
__device__ __forceinline__ float gelu_exact(float x) {
    return 0.5f * x * (1.0f + erff(x * 0.70710678118654752440f));
}

__device__ __forceinline__ void mma_tf32(float d[4], const uint32_t a[4], const uint32_t b[2]) {
    asm volatile(
        "mma.sync.aligned.m16n8k8.row.col.f32.tf32.tf32.f32 "
        "{%0,%1,%2,%3}, {%4,%5,%6,%7}, {%8,%9}, {%0,%1,%2,%3};\n"
        : "+f"(d[0]), "+f"(d[1]), "+f"(d[2]), "+f"(d[3])
        : "r"(a[0]), "r"(a[1]), "r"(a[2]), "r"(a[3]), "r"(b[0]), "r"(b[1]));
}

__device__ __forceinline__ void cp16(float* smem, const float* gmem) {
    uint32_t s = (uint32_t)__cvta_generic_to_shared(smem);
    asm volatile("cp.async.cg.shared.global [%0], [%1], 16;\n" :: "r"(s), "l"(gmem));
}
__device__ __forceinline__ void cp_commit() {
    asm volatile("cp.async.commit_group;\n");
}
template<int N>
__device__ __forceinline__ void cp_wait() {
    asm volatile("cp.async.wait_group %0;\n" :: "n"(N));
}

// ---------------- GEMM ----------------
// C[M,N] = A[M,K] @ B + epilogue.
//   BT=false : B is [K,N] row-major (NN)
//   BT=true  : B is [N,K] row-major (NT, C = A @ B^T)
//   CAUSAL   : skip CTA if its N-tile is fully above the diagonal
//   PVT      : truncate K loop at end of this M-tile (P@V causal structure)
#define EPI_STORE    0
#define EPI_BIAS     1
#define EPI_BIAS_RES 2
#define EPI_GELU     3

template<int EPI, bool BT, bool CAUSAL, bool PVT>
__global__ void __launch_bounds__(256, 1)
gemm_k(const float* __restrict__ A, const float* __restrict__ B,
       const float* __restrict__ bias, const float* __restrict__ res,
       float* __restrict__ C, int M, int N, int K,
       long long aB, long long bB, long long cB)
{
    const int bn = blockIdx.x, bm = blockIdx.y, bz = blockIdx.z;
    if (CAUSAL && bn > 2 * bm + 1) return;   // N-tile entirely above diagonal
    A += (long long)bz * aB;
    B += (long long)bz * bB;
    C += (long long)bz * cB;

    extern __shared__ float sm[];

    const int tid  = threadIdx.x;
    const int lane = tid & 31;
    const int warp = tid >> 5;
    const int wm = (warp >> 1) * 64;   // 4 warps along M (64 rows each)
    const int wn = (warp & 1) * 64;    // 2 warps along N (64 cols each)
    const int g  = lane >> 2;          // groupID
    const int tg = lane & 3;           // thread-in-group
    const int m0 = bm * MT, n0 = bn * NT;

    int ktiles = K / KT;
    if (PVT) { int kt2 = (bm + 1) * (MT / KT); if (kt2 < ktiles) ktiles = kt2; }

    float acc[4][8][4];
#pragma unroll
    for (int i = 0; i < 4; i++)
#pragma unroll
        for (int j = 0; j < 8; j++)
#pragma unroll
            for (int r = 0; r < 4; r++) acc[i][j][r] = 0.0f;

    auto issue = [&](int stage, int kt) {
        float* sA = sm + stage * STAGE_F;
        float* sB = sA + A_STAGE;
        // A tile: 256 rows x 32 floats = 2048 float4 chunks
#pragma unroll
        for (int i = 0; i < 8; i++) {
            const int idx = tid + i * 256;
            const int row = idx >> 3, ch = idx & 7;
            cp16(&sA[row * ASTRIDE + ch * 4],
                 A + (size_t)(m0 + row) * K + kt * KT + ch * 4);
        }
        if (!BT) {
            // B tile: 32 k-rows x 128 floats = 1024 chunks
#pragma unroll
            for (int i = 0; i < 4; i++) {
                const int idx = tid + i * 256;
                const int row = idx >> 5, ch = idx & 31;
                cp16(&sB[row * BSTRIDE_NN + ch * 4],
                     B + (size_t)(kt * KT + row) * N + n0 + ch * 4);
            }
        } else {
            // B tile (n-major): 128 n-rows x 32 floats = 1024 chunks
#pragma unroll
            for (int i = 0; i < 4; i++) {
                const int idx = tid + i * 256;
                const int row = idx >> 3, ch = idx & 7;
                cp16(&sB[row * BSTRIDE_NT + ch * 4],
                     B + (size_t)(n0 + row) * K + kt * KT + ch * 4);
            }
        }
    };

    // prologue: 2 stages in flight
    issue(0, 0); cp_commit();
    issue(1, 1); cp_commit();

    for (int kt = 0; kt < ktiles; kt++) {
        cp_wait<STAGES - 2>();
        __syncthreads();

        const int nkt = kt + STAGES - 1;
        if (nkt < ktiles) issue(nkt % STAGES, nkt);
        cp_commit();

        const float* sA = sm + (kt % STAGES) * STAGE_F;
        const float* sB = sA + A_STAGE;

#pragma unroll
        for (int ks = 0; ks < 4; ks++) {
            const int k0 = ks * 8;
            uint32_t af[4][4];
#pragma unroll
            for (int mi = 0; mi < 4; mi++) {
                const int r = wm + mi * 16 + g;
                af[mi][0] = __float_as_uint(sA[(r    ) * ASTRIDE + k0 + tg    ]);
                af[mi][1] = __float_as_uint(sA[(r + 8) * ASTRIDE + k0 + tg    ]);
                af[mi][2] = __float_as_uint(sA[(r    ) * ASTRIDE + k0 + tg + 4]);
                af[mi][3] = __float_as_uint(sA[(r + 8) * ASTRIDE + k0 + tg + 4]);
            }
            uint32_t bf[8][2];
#pragma unroll
            for (int ni = 0; ni < 8; ni++) {
                const int c = wn + ni * 8 + g;
                if (!BT) {
                    bf[ni][0] = __float_as_uint(sB[(k0 + tg    ) * BSTRIDE_NN + c]);
                    bf[ni][1] = __float_as_uint(sB[(k0 + tg + 4) * BSTRIDE_NN + c]);
                } else {
                    bf[ni][0] = __float_as_uint(sB[c * BSTRIDE_NT + k0 + tg    ]);
                    bf[ni][1] = __float_as_uint(sB[c * BSTRIDE_NT + k0 + tg + 4]);
                }
            }
#pragma unroll
            for (int mi = 0; mi < 4; mi++)
#pragma unroll
                for (int ni = 0; ni < 8; ni++)
                    mma_tf32(acc[mi][ni], af[mi], bf[ni]);
        }
        __syncthreads();
    }

    // epilogue
#pragma unroll
    for (int mi = 0; mi < 4; mi++) {
#pragma unroll
        for (int ni = 0; ni < 8; ni++) {
            const int r = m0 + wm + mi * 16 + g;
            const int c = n0 + wn + ni * 8 + tg * 2;
#pragma unroll
            for (int h = 0; h < 2; h++) {
                const int rr = r + h * 8;
                float v0 = acc[mi][ni][h * 2 + 0];
                float v1 = acc[mi][ni][h * 2 + 1];
                if (EPI == EPI_BIAS || EPI == EPI_BIAS_RES || EPI == EPI_GELU) {
                    v0 += bias[c]; v1 += bias[c + 1];
                }
                if (EPI == EPI_BIAS_RES) {
                    v0 += res[(size_t)rr * N + c];
                    v1 += res[(size_t)rr * N + c + 1];
                }
                if (EPI == EPI_GELU) { v0 = gelu_exact(v0); v1 = gelu_exact(v1); }
                *(float2*)&C[(size_t)rr * N + c] = make_float2(v0, v1);
            }
        }
    }
}

// ---------------- RMSNorm ----------------
__global__ void __launch_bounds__(256, 1)
rmsnorm_k(const float* __restrict__ x, const float* __restrict__ w, float* __restrict__ o)
{
    __shared__ float red[8];
    __shared__ float bc;
    const int row = blockIdx.x;
    const size_t base = (size_t)row * DIM;
    const int tid = threadIdx.x, lane = tid & 31, warp = tid >> 5;

    float4 xv = ((const float4*)(x + base))[tid];
    float ss = xv.x * xv.x + xv.y * xv.y + xv.z * xv.z + xv.w * xv.w;
#pragma unroll
    for (int off = 16; off; off >>= 1) ss += __shfl_xor_sync(0xffffffffu, ss, off);
    if (lane == 0) red[warp] = ss;
    __syncthreads();
    if (tid == 0) {
        float t = 0.0f;
#pragma unroll
        for (int i = 0; i < 8; i++) t += red[i];
        bc = rsqrtf(t * (1.0f / DIM) + 1e-6f);
    }
    __syncthreads();
    const float inv = bc;
    float4 wv = ((const float4*)w)[tid];
    float4 ov;
    ov.x = xv.x * inv * wv.x; ov.y = xv.y * inv * wv.y;
    ov.z = xv.z * inv * wv.z; ov.w = xv.w * inv * wv.w;
    ((float4*)(o + base))[tid] = ov;
}

// ---------------- causal softmax (in place, zero-fill to 256-tile edge) ----------------
__global__ void __launch_bounds__(256, 1)
softmax_k(float* __restrict__ s)
{
    __shared__ float red[8];
    __shared__ float bc;
    const int t = blockIdx.x, b = blockIdx.y;
    float* row = s + ((size_t)b * SEQ + (size_t)t) * SEQ;
    const int L = t + 1;
    const int tid = threadIdx.x, lane = tid & 31, warp = tid >> 5;
    const float scale = 0.03125f;  // 1/sqrt(1024)

    float m = -3.4e38f;
    for (int j = tid; j < L; j += 256) m = fmaxf(m, row[j]);
#pragma unroll
    for (int off = 16; off; off >>= 1) m = fmaxf(m, __shfl_xor_sync(0xffffffffu, m, off));
    if (lane == 0) red[warp] = m;
    __syncthreads();
    if (tid == 0) {
        float mm = red[0];
#pragma unroll
        for (int i = 1; i < 8; i++) mm = fmaxf(mm, red[i]);
        bc = mm;
    }
    __syncthreads();
    const float mm = bc;
    __syncthreads();

    float sum = 0.0f;
    for (int j = tid; j < L; j += 256) {
        float e = expf((row[j] - mm) * scale);
        row[j] = e;
        sum += e;
    }
#pragma unroll
    for (int off = 16; off; off >>= 1) sum += __shfl_xor_sync(0xffffffffu, sum, off);
    if (lane == 0) red[warp] = sum;
    __syncthreads();
    if (tid == 0) {
        float ss = 0.0f;
#pragma unroll
        for (int i = 0; i < 8; i++) ss += red[i];
        bc = 1.0f / ss;
    }
    __syncthreads();
    const float inv = bc;
    for (int j = tid; j < L; j += 256) row[j] *= inv;

    // zero-fill masked region up to this row's 256-tile edge (P@V reads it)
    const int jend = ((t >> 8) + 1) << 8;
    for (int j = L + tid; j < jend; j += 256) row[j] = 0.0f;
}

// ---------------- launch ----------------
extern "C" void kernel_launch(void* const* d_in, const int* in_sizes, int n_in,
                              void* d_out, int out_size)
{
    (void)in_sizes; (void)n_in; (void)out_size;
    const float* x   = (const float*)d_in[0];
    const float* anw = (const float*)d_in[1];
    const float* mnw = (const float*)d_in[2];
    const float* wq  = (const float*)d_in[3];
    const float* bq  = (const float*)d_in[4];
    const float* wk  = (const float*)d_in[5];
    const float* bk  = (const float*)d_in[6];
    const float* wv  = (const float*)d_in[7];
    const float* bv  = (const float*)d_in[8];
    const float* wo  = (const float*)d_in[9];
    const float* bo  = (const float*)d_in[10];
    const float* w1  = (const float*)d_in[11];
    const float* b1  = (const float*)d_in[12];
    const float* w2  = (const float*)d_in[13];
    const float* b2  = (const float*)d_in[14];
    float* out = (float*)d_out;

    float *xn, *q, *k, *v, *attn, *xmid, *h1, *sc;
    cudaGetSymbolAddress((void**)&xn,   g_xn);
    cudaGetSymbolAddress((void**)&q,    g_q);
    cudaGetSymbolAddress((void**)&k,    g_k);
    cudaGetSymbolAddress((void**)&v,    g_v);
    cudaGetSymbolAddress((void**)&attn, g_attn);
    cudaGetSymbolAddress((void**)&xmid, g_xmid);
    cudaGetSymbolAddress((void**)&h1,   g_h1);
    cudaGetSymbolAddress((void**)&sc,   g_sc);

    // allow >48KB dynamic smem for every instantiation we use
    cudaFuncSetAttribute(gemm_k<EPI_BIAS,     false, false, false>,
                         cudaFuncAttributeMaxDynamicSharedMemorySize, SMEM_BYTES);
    cudaFuncSetAttribute(gemm_k<EPI_STORE,    true,  true,  false>,
                         cudaFuncAttributeMaxDynamicSharedMemorySize, SMEM_BYTES);
    cudaFuncSetAttribute(gemm_k<EPI_STORE,    false, false, true >,
                         cudaFuncAttributeMaxDynamicSharedMemorySize, SMEM_BYTES);
    cudaFuncSetAttribute(gemm_k<EPI_BIAS_RES, false, false, false>,
                         cudaFuncAttributeMaxDynamicSharedMemorySize, SMEM_BYTES);
    cudaFuncSetAttribute(gemm_k<EPI_GELU,     false, false, false>,
                         cudaFuncAttributeMaxDynamicSharedMemorySize, SMEM_BYTES);

    const long long qkB = (long long)SEQ * DIM;
    const long long scB = (long long)SEQ * SEQ;

    // 1) xn = rmsnorm(x) * attn_norm_w
    rmsnorm_k<<<ROWS, 256>>>(x, anw, xn);

    // 2) Q, K, V = xn @ W + b
    gemm_k<EPI_BIAS, false, false, false><<<dim3(DIM/NT, ROWS/MT, 1), 256, SMEM_BYTES>>>(
        xn, wq, bq, nullptr, q, ROWS, DIM, DIM, 0, 0, 0);
    gemm_k<EPI_BIAS, false, false, false><<<dim3(DIM/NT, ROWS/MT, 1), 256, SMEM_BYTES>>>(
        xn, wk, bk, nullptr, k, ROWS, DIM, DIM, 0, 0, 0);
    gemm_k<EPI_BIAS, false, false, false><<<dim3(DIM/NT, ROWS/MT, 1), 256, SMEM_BYTES>>>(
        xn, wv, bv, nullptr, v, ROWS, DIM, DIM, 0, 0, 0);

    // 3) scores = Q @ K^T (per batch, causal block-skip)
    gemm_k<EPI_STORE, true, true, false><<<dim3(SEQ/NT, SEQ/MT, BATCH), 256, SMEM_BYTES>>>(
        q, k, nullptr, nullptr, sc, SEQ, SEQ, DIM, qkB, qkB, scB);

    // 4) causal softmax (scale 1/32 inside)
    softmax_k<<<dim3(SEQ, BATCH), 256>>>(sc);

    // 5) attn = P @ V (K loop truncated at causal tile edge)
    gemm_k<EPI_STORE, false, false, true><<<dim3(DIM/NT, SEQ/MT, BATCH), 256, SMEM_BYTES>>>(
        sc, v, nullptr, nullptr, attn, SEQ, DIM, SEQ, scB, qkB, qkB);

    // 6) xmid = x + attn @ wo + bo
    gemm_k<EPI_BIAS_RES, false, false, false><<<dim3(DIM/NT, ROWS/MT, 1), 256, SMEM_BYTES>>>(
        attn, wo, bo, x, xmid, ROWS, DIM, DIM, 0, 0, 0);

    // 7) h = rmsnorm(xmid) * mlp_norm_w
    rmsnorm_k<<<ROWS, 256>>>(xmid, mnw, xn);

    // 8) h1 = gelu(h @ w1 + b1)
    gemm_k<EPI_GELU, false, false, false><<<dim3(HID/NT, ROWS/MT, 1), 256, SMEM_BYTES>>>(
        xn, w1, b1, nullptr, h1, ROWS, HID, DIM, 0, 0, 0);

    // 9) out = xmid + h1 @ w2 + b2
    gemm_k<EPI_BIAS_RES, false, false, false><<<dim3(DIM/NT, ROWS/MT, 1), 256, SMEM_BYTES>>>(
        h1, w2, b2, xmid, out, ROWS, DIM, HID, 0, 0, 0);
}

// round 4
// speedup vs baseline: 1.2487x; 1.0210x over previous
#include <cuda_runtime.h>
#include <cstdint>
#include <math.h>

#define BATCH 8
#define SEQ   2048
#define DIM   1024
#define HID   4096
#define ROWS  (BATCH*SEQ)   /* 16384 */

// GEMM tiling: CTA 256x128x32, 8 warps of 64x64
#define MT 256
#define NT 128
#define KT 32
#define STAGES 3
#define ASTRIDE 36
#define BSTRIDE 36
#define A_STAGE (MT*ASTRIDE)            /* 9216 floats */
#define B_STAGE (NT*BSTRIDE)            /* 4608 floats */
#define STAGE_F (A_STAGE + B_STAGE)     /* 13824 floats */
#define SMEM_BYTES (STAGES*STAGE_F*4)   /* 165888 bytes */
#define VT_STRIDE 260                   /* V^T epilogue staging stride */

// ---------------- scratch (allocation-free: __device__ globals) ----------------
static __device__ float g_xn  [(size_t)ROWS*DIM];
static __device__ float g_q   [(size_t)ROWS*DIM];
static __device__ float g_k   [(size_t)ROWS*DIM];
static __device__ float g_vt  [(size_t)ROWS*DIM];     // V^T: [b][d][s]
static __device__ float g_attn[(size_t)ROWS*DIM];
static __device__ float g_xmid[(size_t)ROWS*DIM];
static __device__ float g_h1  [(size_t)ROWS*HID];
static __device__ float g_sc  [(size_t)BATCH*SEQ*SEQ];
// weights transposed to [N][K]
static __device__ float g_wqt [(size_t)DIM*DIM];
static __device__ float g_wkt [(size_t)DIM*DIM];
static __device__ float g_wvt [(size_t)DIM*DIM];
static __device__ float g_wot [(size_t)DIM*DIM];
static __device__ float g_w1t [(size_t)HID*DIM];
static __device__ float g_w2t [(size_t)DIM*HID];

// ---------------- helpers ----------------
__device__ __forceinline__ float gelu_exact(float x) {
    return 0.5f * x * (1.0f + erff(x * 0.70710678118654752440f));
}

__device__ __forceinline__ void mma_tf32(float d[4], const uint32_t a[4], const uint32_t b[2]) {
    asm volatile(
        "mma.sync.aligned.m16n8k8.row.col.f32.tf32.tf32.f32 "
        "{%0,%1,%2,%3}, {%4,%5,%6,%7}, {%8,%9}, {%0,%1,%2,%3};\n"
        : "+f"(d[0]), "+f"(d[1]), "+f"(d[2]), "+f"(d[3])
        : "r"(a[0]), "r"(a[1]), "r"(a[2]), "r"(a[3]), "r"(b[0]), "r"(b[1]));
}

__device__ __forceinline__ void ldm4(uint32_t r[4], const float* p) {
    uint32_t a = (uint32_t)__cvta_generic_to_shared(p);
    asm volatile("ldmatrix.sync.aligned.m8n8.x4.shared.b16 {%0,%1,%2,%3}, [%4];\n"
                 : "=r"(r[0]), "=r"(r[1]), "=r"(r[2]), "=r"(r[3]) : "r"(a));
}

__device__ __forceinline__ void cp16(float* smem, const float* gmem) {
    uint32_t s = (uint32_t)__cvta_generic_to_shared(smem);
    asm volatile("cp.async.cg.shared.global [%0], [%1], 16;\n" :: "r"(s), "l"(gmem));
}
__device__ __forceinline__ void cp_commit() { asm volatile("cp.async.commit_group;\n"); }
template<int N>
__device__ __forceinline__ void cp_wait() { asm volatile("cp.async.wait_group %0;\n" :: "n"(N)); }

// ---------------- GEMM ----------------
// C[M,N] = A[M,K] @ B^T + epi, where B is stored [N][K] (k-major rows).
//   CAUSAL : skip CTA if N-tile fully above diagonal (M-tile 256, N-tile 128)
//   PVT    : truncate K loop at end of this M-tile (P@V causal structure)
#define EPI_STORE    0
#define EPI_BIAS     1
#define EPI_BIAS_RES 2
#define EPI_GELU     3
#define EPI_VT       4   /* bias + write transposed as V^T [b][d][s] */

template<int EPI, bool CAUSAL, bool PVT>
__global__ void __launch_bounds__(256, 1)
gemm_k(const float* __restrict__ A, const float* __restrict__ B,
       const float* __restrict__ bias, const float* __restrict__ res,
       float* __restrict__ C, int M, int N, int K,
       long long aB, long long bB, long long cB)
{
    const int bn = blockIdx.x, bm = blockIdx.y, bz = blockIdx.z;
    if (CAUSAL && bn > 2 * bm + 1) return;
    A += (long long)bz * aB;
    B += (long long)bz * bB;
    C += (long long)bz * cB;

    extern __shared__ float sm[];

    const int tid  = threadIdx.x;
    const int lane = tid & 31;
    const int warp = tid >> 5;
    const int wm = (warp >> 1) * 64;   // 4 warps along M
    const int wn = (warp & 1) * 64;    // 2 warps along N
    const int g  = lane >> 2;
    const int tg = lane & 3;
    const int m0 = bm * MT, n0 = bn * NT;

    int ktiles = K / KT;
    if (PVT) { int kt2 = (bm + 1) * (MT / KT); if (kt2 < ktiles) ktiles = kt2; }

    float acc[4][8][4];
#pragma unroll
    for (int i = 0; i < 4; i++)
#pragma unroll
        for (int j = 0; j < 8; j++)
#pragma unroll
            for (int r = 0; r < 4; r++) acc[i][j][r] = 0.0f;

    // ldmatrix per-lane row/col selectors
    const int l8 = lane & 7, q = lane >> 3;
    const int a_row = (q & 1) * 8 + l8;          // A: mats {r0-7,k0-3},{r8-15,k0-3},{r0-7,k4-7},{r8-15,k4-7}
    const int a_col = (q >> 1) * 4;
    const int b_row = (q >> 1) * 8 + l8;         // B: mats {n0-7,k0-3},{n0-7,k4-7},{n8-15,k0-3},{n8-15,k4-7}
    const int b_col = (q & 1) * 4;

    auto issue = [&](int stage, int kt) {
        float* sA = sm + stage * STAGE_F;
        float* sB = sA + A_STAGE;
#pragma unroll
        for (int i = 0; i < 8; i++) {             // A: 256 rows x 8 chunks of 16B
            const int idx = tid + i * 256;
            const int row = idx >> 3, ch = idx & 7;
            cp16(&sA[row * ASTRIDE + ch * 4],
                 A + (size_t)(m0 + row) * K + kt * KT + ch * 4);
        }
#pragma unroll
        for (int i = 0; i < 4; i++) {             // B: 128 n-rows x 8 chunks
            const int idx = tid + i * 256;
            const int row = idx >> 3, ch = idx & 7;
            cp16(&sB[row * BSTRIDE + ch * 4],
                 B + (size_t)(n0 + row) * K + kt * KT + ch * 4);
        }
    };

    issue(0, 0); cp_commit();
    issue(1, 1); cp_commit();

    for (int kt = 0; kt < ktiles; kt++) {
        cp_wait<STAGES - 2>();
        __syncthreads();

        const int nkt = kt + STAGES - 1;
        if (nkt < ktiles) issue(nkt % STAGES, nkt);
        cp_commit();

        const float* sA = sm + (kt % STAGES) * STAGE_F;
        const float* sB = sA + A_STAGE;

#pragma unroll
        for (int ks = 0; ks < 4; ks++) {
            const int k0 = ks * 8;
            uint32_t af[4][4];
#pragma unroll
            for (int mi = 0; mi < 4; mi++)
                ldm4(af[mi], &sA[(wm + mi * 16 + a_row) * ASTRIDE + k0 + a_col]);
            uint32_t bf[8][2];
#pragma unroll
            for (int np = 0; np < 4; np++) {
                uint32_t r[4];
                ldm4(r, &sB[(wn + np * 16 + b_row) * BSTRIDE + k0 + b_col]);
                bf[2*np][0] = r[0]; bf[2*np][1] = r[1];
                bf[2*np+1][0] = r[2]; bf[2*np+1][1] = r[3];
            }
#pragma unroll
            for (int mi = 0; mi < 4; mi++)
#pragma unroll
                for (int ni = 0; ni < 8; ni++)
                    mma_tf32(acc[mi][ni], af[mi], bf[ni]);
        }
        __syncthreads();
    }

    if (EPI != EPI_VT) {
#pragma unroll
        for (int mi = 0; mi < 4; mi++) {
#pragma unroll
            for (int ni = 0; ni < 8; ni++) {
                const int r = m0 + wm + mi * 16 + g;
                const int c = n0 + wn + ni * 8 + tg * 2;
#pragma unroll
                for (int h = 0; h < 2; h++) {
                    const int rr = r + h * 8;
                    float v0 = acc[mi][ni][h * 2 + 0];
                    float v1 = acc[mi][ni][h * 2 + 1];
                    if (EPI == EPI_BIAS || EPI == EPI_BIAS_RES || EPI == EPI_GELU) {
                        v0 += bias[c]; v1 += bias[c + 1];
                    }
                    if (EPI == EPI_BIAS_RES) {
                        v0 += res[(size_t)rr * N + c];
                        v1 += res[(size_t)rr * N + c + 1];
                    }
                    if (EPI == EPI_GELU) { v0 = gelu_exact(v0); v1 = gelu_exact(v1); }
                    *(float2*)&C[(size_t)rr * N + c] = make_float2(v0, v1);
                }
            }
        }
    } else {
        // stage C tile transposed in smem as [n][m] then write V^T coalesced
        float* stg = sm;   // 128 x VT_STRIDE floats = 133120 B < SMEM_BYTES
#pragma unroll
        for (int mi = 0; mi < 4; mi++) {
#pragma unroll
            for (int ni = 0; ni < 8; ni++) {
                const int c = wn + ni * 8 + tg * 2;
#pragma unroll
                for (int h = 0; h < 2; h++) {
                    const int r = wm + mi * 16 + g + h * 8;
                    stg[(c    ) * VT_STRIDE + r] = acc[mi][ni][h * 2 + 0];
                    stg[(c + 1) * VT_STRIDE + r] = acc[mi][ni][h * 2 + 1];
                }
            }
        }
        __syncthreads();
        const int b = m0 >> 11, t0 = m0 & 2047;
        for (int nr = warp * 16; nr < warp * 16 + 16; nr++) {
            const int n = n0 + nr;
            const float bn_ = bias[n];
            float* dst = C + ((size_t)b * DIM + n) * SEQ + t0;
#pragma unroll
            for (int i = 0; i < 2; i++) {
                const int m = lane * 4 + i * 128;
                float4 v = *(float4*)&stg[nr * VT_STRIDE + m];
                v.x += bn_; v.y += bn_; v.z += bn_; v.w += bn_;
                *(float4*)&dst[m] = v;
            }
        }
    }
}

// ---------------- weight transpose: w[K][N] -> wt[N][K] ----------------
__global__ void wtrans_k(const float* __restrict__ w, float* __restrict__ wt, int Kd, int Nd)
{
    __shared__ float t[32][33];
    const int bx = blockIdx.x, by = blockIdx.y;
    const int tx = threadIdx.x, ty = threadIdx.y;   // (32,8)
#pragma unroll
    for (int j = 0; j < 4; j++)
        t[ty + j * 8][tx] = w[(size_t)(by * 32 + ty + j * 8) * Nd + bx * 32 + tx];
    __syncthreads();
#pragma unroll
    for (int j = 0; j < 4; j++)
        wt[(size_t)(bx * 32 + ty + j * 8) * Kd + by * 32 + tx] = t[tx][ty + j * 8];
}

// ---------------- RMSNorm ----------------
__global__ void __launch_bounds__(256, 1)
rmsnorm_k(const float* __restrict__ x, const float* __restrict__ w, float* __restrict__ o)
{
    __shared__ float red[8];
    __shared__ float bc;
    const int row = blockIdx.x;
    const size_t base = (size_t)row * DIM;
    const int tid = threadIdx.x, lane = tid & 31, warp = tid >> 5;

    float4 xv = ((const float4*)(x + base))[tid];
    float ss = xv.x * xv.x + xv.y * xv.y + xv.z * xv.z + xv.w * xv.w;
#pragma unroll
    for (int off = 16; off; off >>= 1) ss += __shfl_xor_sync(0xffffffffu, ss, off);
    if (lane == 0) red[warp] = ss;
    __syncthreads();
    if (tid == 0) {
        float t = 0.0f;
#pragma unroll
        for (int i = 0; i < 8; i++) t += red[i];
        bc = rsqrtf(t * (1.0f / DIM) + 1e-6f);
    }
    __syncthreads();
    const float inv = bc;
    float4 wv = ((const float4*)w)[tid];
    float4 ov;
    ov.x = xv.x * inv * wv.x; ov.y = xv.y * inv * wv.y;
    ov.z = xv.z * inv * wv.z; ov.w = xv.w * inv * wv.w;
    ((float4*)(o + base))[tid] = ov;
}

// ---------------- causal softmax (in place, zero-fill to 256-tile edge) ----------------
__global__ void __launch_bounds__(256, 1)
softmax_k(float* __restrict__ s)
{
    __shared__ float red[8];
    __shared__ float bc;
    const int t = blockIdx.x, b = blockIdx.y;
    float* row = s + ((size_t)b * SEQ + (size_t)t) * SEQ;
    const int L = t + 1;
    const int tid = threadIdx.x, lane = tid & 31, warp = tid >> 5;
    const float scale = 0.03125f;  // 1/sqrt(1024)

    float m = -3.4e38f;
    for (int j = tid; j < L; j += 256) m = fmaxf(m, row[j]);
#pragma unroll
    for (int off = 16; off; off >>= 1) m = fmaxf(m, __shfl_xor_sync(0xffffffffu, m, off));
    if (lane == 0) red[warp] = m;
    __syncthreads();
    if (tid == 0) {
        float mm = red[0];
#pragma unroll
        for (int i = 1; i < 8; i++) mm = fmaxf(mm, red[i]);
        bc = mm;
    }
    __syncthreads();
    const float mm = bc;
    __syncthreads();

    float sum = 0.0f;
    for (int j = tid; j < L; j += 256) {
        float e = expf((row[j] - mm) * scale);
        row[j] = e;
        sum += e;
    }
#pragma unroll
    for (int off = 16; off; off >>= 1) sum += __shfl_xor_sync(0xffffffffu, sum, off);
    if (lane == 0) red[warp] = sum;
    __syncthreads();
    if (tid == 0) {
        float ss = 0.0f;
#pragma unroll
        for (int i = 0; i < 8; i++) ss += red[i];
        bc = 1.0f / ss;
    }
    __syncthreads();
    const float inv = bc;
    for (int j = tid; j < L; j += 256) row[j] *= inv;

    const int jend = ((t >> 8) + 1) << 8;
    for (int j = L + tid; j < jend; j += 256) row[j] = 0.0f;
}

// ---------------- launch ----------------
extern "C" void kernel_launch(void* const* d_in, const int* in_sizes, int n_in,
                              void* d_out, int out_size)
{
    (void)in_sizes; (void)n_in; (void)out_size;
    const float* x   = (const float*)d_in[0];
    const float* anw = (const float*)d_in[1];
    const float* mnw = (const float*)d_in[2];
    const float* wq  = (const float*)d_in[3];
    const float* bq  = (const float*)d_in[4];
    const float* wk  = (const float*)d_in[5];
    const float* bk  = (const float*)d_in[6];
    const float* wv  = (const float*)d_in[7];
    const float* bv  = (const float*)d_in[8];
    const float* wo  = (const float*)d_in[9];
    const float* bo  = (const float*)d_in[10];
    const float* w1  = (const float*)d_in[11];
    const float* b1  = (const float*)d_in[12];
    const float* w2  = (const float*)d_in[13];
    const float* b2  = (const float*)d_in[14];
    float* out = (float*)d_out;

    float *xn, *q, *k, *vt, *attn, *xmid, *h1, *sc;
    float *wqt, *wkt, *wvt, *wot, *w1t, *w2t;
    cudaGetSymbolAddress((void**)&xn,   g_xn);
    cudaGetSymbolAddress((void**)&q,    g_q);
    cudaGetSymbolAddress((void**)&k,    g_k);
    cudaGetSymbolAddress((void**)&vt,   g_vt);
    cudaGetSymbolAddress((void**)&attn, g_attn);
    cudaGetSymbolAddress((void**)&xmid, g_xmid);
    cudaGetSymbolAddress((void**)&h1,   g_h1);
    cudaGetSymbolAddress((void**)&sc,   g_sc);
    cudaGetSymbolAddress((void**)&wqt,  g_wqt);
    cudaGetSymbolAddress((void**)&wkt,  g_wkt);
    cudaGetSymbolAddress((void**)&wvt,  g_wvt);
    cudaGetSymbolAddress((void**)&wot,  g_wot);
    cudaGetSymbolAddress((void**)&w1t,  g_w1t);
    cudaGetSymbolAddress((void**)&w2t,  g_w2t);

    cudaFuncSetAttribute(gemm_k<EPI_BIAS,     false, false>,
                         cudaFuncAttributeMaxDynamicSharedMemorySize, SMEM_BYTES);
    cudaFuncSetAttribute(gemm_k<EPI_VT,       false, false>,
                         cudaFuncAttributeMaxDynamicSharedMemorySize, SMEM_BYTES);
    cudaFuncSetAttribute(gemm_k<EPI_STORE,    true,  false>,
                         cudaFuncAttributeMaxDynamicSharedMemorySize, SMEM_BYTES);
    cudaFuncSetAttribute(gemm_k<EPI_STORE,    false, true >,
                         cudaFuncAttributeMaxDynamicSharedMemorySize, SMEM_BYTES);
    cudaFuncSetAttribute(gemm_k<EPI_BIAS_RES, false, false>,
                         cudaFuncAttributeMaxDynamicSharedMemorySize, SMEM_BYTES);
    cudaFuncSetAttribute(gemm_k<EPI_GELU,     false, false>,
                         cudaFuncAttributeMaxDynamicSharedMemorySize, SMEM_BYTES);

    const long long SD = (long long)SEQ * DIM;
    const long long SS = (long long)SEQ * SEQ;
    const dim3 wb(32, 8);

    // 0) transpose weights to [N][K]
    wtrans_k<<<dim3(DIM/32, DIM/32), wb>>>(wq, wqt, DIM, DIM);
    wtrans_k<<<dim3(DIM/32, DIM/32), wb>>>(wk, wkt, DIM, DIM);
    wtrans_k<<<dim3(DIM/32, DIM/32), wb>>>(wv, wvt, DIM, DIM);
    wtrans_k<<<dim3(DIM/32, DIM/32), wb>>>(wo, wot, DIM, DIM);
    wtrans_k<<<dim3(HID/32, DIM/32), wb>>>(w1, w1t, DIM, HID);
    wtrans_k<<<dim3(DIM/32, HID/32), wb>>>(w2, w2t, HID, DIM);

    // 1) xn = rmsnorm(x) * attn_norm_w
    rmsnorm_k<<<ROWS, 256>>>(x, anw, xn);

    // 2) Q, K, V (V written transposed as V^T)
    gemm_k<EPI_BIAS, false, false><<<dim3(DIM/NT, ROWS/MT, 1), 256, SMEM_BYTES>>>(
        xn, wqt, bq, nullptr, q, ROWS, DIM, DIM, 0, 0, 0);
    gemm_k<EPI_BIAS, false, false><<<dim3(DIM/NT, ROWS/MT, 1), 256, SMEM_BYTES>>>(
        xn, wkt, bk, nullptr, k, ROWS, DIM, DIM, 0, 0, 0);
    gemm_k<EPI_VT, false, false><<<dim3(DIM/NT, ROWS/MT, 1), 256, SMEM_BYTES>>>(
        xn, wvt, bv, nullptr, vt, ROWS, DIM, DIM, 0, 0, 0);

    // 3) scores = Q @ K^T (per batch, causal block-skip)
    gemm_k<EPI_STORE, true, false><<<dim3(SEQ/NT, SEQ/MT, BATCH), 256, SMEM_BYTES>>>(
        q, k, nullptr, nullptr, sc, SEQ, SEQ, DIM, SD, SD, SS);

    // 4) causal softmax
    softmax_k<<<dim3(SEQ, BATCH), 256>>>(sc);

    // 5) attn = P @ V  (B = V^T [d][s], K loop truncated)
    gemm_k<EPI_STORE, false, true><<<dim3(DIM/NT, SEQ/MT, BATCH), 256, SMEM_BYTES>>>(
        sc, vt, nullptr, nullptr, attn, SEQ, DIM, SEQ, SS, SD, SD);

    // 6) xmid = x + attn @ wo + bo
    gemm_k<EPI_BIAS_RES, false, false><<<dim3(DIM/NT, ROWS/MT, 1), 256, SMEM_BYTES>>>(
        attn, wot, bo, x, xmid, ROWS, DIM, DIM, 0, 0, 0);

    // 7) h = rmsnorm(xmid) * mlp_norm_w
    rmsnorm_k<<<ROWS, 256>>>(xmid, mnw, xn);

    // 8) h1 = gelu(h @ w1 + b1)
    gemm_k<EPI_GELU, false, false><<<dim3(HID/NT, ROWS/MT, 1), 256, SMEM_BYTES>>>(
        xn, w1t, b1, nullptr, h1, ROWS, HID, DIM, 0, 0, 0);

    // 9) out = xmid + h1 @ w2 + b2
    gemm_k<EPI_BIAS_RES, false, false><<<dim3(DIM/NT, ROWS/MT, 1), 256, SMEM_BYTES>>>(
        h1, w2t, b2, xmid, out, ROWS, DIM, HID, 0, 0, 0);
}

// round 5
// speedup vs baseline: 1.4623x; 1.1711x over previous
#include <cuda_runtime.h>
#include <cstdint>
#include <math.h>

#define BATCH 8
#define SEQ   2048
#define DIM   1024
#define HID   4096
#define ROWS  (BATCH*SEQ)   /* 16384 */

// GEMM tiling: CTA 128x128x32, 8 warps of 32x64, 2 CTAs/SM
#define MT 128
#define NT 128
#define KT 32
#define STAGES 3
#define ASTRIDE 36
#define BSTRIDE 36
#define A_STAGE (MT*ASTRIDE)            /* 4608 floats */
#define B_STAGE (NT*BSTRIDE)            /* 4608 floats */
#define STAGE_F (A_STAGE + B_STAGE)     /* 9216 floats */
#define SMEM_BYTES (STAGES*STAGE_F*4)   /* 110592 bytes -> 2 CTAs/SM */
#define VT_STRIDE 132                   /* V^T epilogue staging stride */

// ---------------- scratch (allocation-free: __device__ globals) ----------------
static __device__ float g_xn  [(size_t)ROWS*DIM];
static __device__ float g_q   [(size_t)ROWS*DIM];
static __device__ float g_k   [(size_t)ROWS*DIM];
static __device__ float g_vt  [(size_t)ROWS*DIM];     // V^T: [b][d][s]
static __device__ float g_attn[(size_t)ROWS*DIM];
static __device__ float g_xmid[(size_t)ROWS*DIM];
static __device__ float g_h1  [(size_t)ROWS*HID];
static __device__ float g_sc  [(size_t)BATCH*SEQ*SEQ];
// weights transposed to [N][K]
static __device__ float g_wqt [(size_t)DIM*DIM];
static __device__ float g_wkt [(size_t)DIM*DIM];
static __device__ float g_wvt [(size_t)DIM*DIM];
static __device__ float g_wot [(size_t)DIM*DIM];
static __device__ float g_w1t [(size_t)HID*DIM];
static __device__ float g_w2t [(size_t)DIM*HID];

// ---------------- helpers ----------------
__device__ __forceinline__ float gelu_exact(float x) {
    return 0.5f * x * (1.0f + erff(x * 0.70710678118654752440f));
}

__device__ __forceinline__ void mma_tf32(float d[4], const uint32_t a[4], const uint32_t b[2]) {
    asm volatile(
        "mma.sync.aligned.m16n8k8.row.col.f32.tf32.tf32.f32 "
        "{%0,%1,%2,%3}, {%4,%5,%6,%7}, {%8,%9}, {%0,%1,%2,%3};\n"
        : "+f"(d[0]), "+f"(d[1]), "+f"(d[2]), "+f"(d[3])
        : "r"(a[0]), "r"(a[1]), "r"(a[2]), "r"(a[3]), "r"(b[0]), "r"(b[1]));
}

__device__ __forceinline__ void ldm4(uint32_t r[4], const float* p) {
    uint32_t a = (uint32_t)__cvta_generic_to_shared(p);
    asm volatile("ldmatrix.sync.aligned.m8n8.x4.shared.b16 {%0,%1,%2,%3}, [%4];\n"
                 : "=r"(r[0]), "=r"(r[1]), "=r"(r[2]), "=r"(r[3]) : "r"(a));
}

__device__ __forceinline__ void cp16(float* smem, const float* gmem) {
    uint32_t s = (uint32_t)__cvta_generic_to_shared(smem);
    asm volatile("cp.async.cg.shared.global [%0], [%1], 16;\n" :: "r"(s), "l"(gmem));
}
__device__ __forceinline__ void cp_commit() { asm volatile("cp.async.commit_group;\n"); }
template<int N>
__device__ __forceinline__ void cp_wait() { asm volatile("cp.async.wait_group %0;\n" :: "n"(N)); }

// ---------------- GEMM ----------------
// C[M,N] = A[M,K] @ B^T + epi, where B is stored [N][K] (k-major rows).
//   CAUSAL : skip CTA if N-tile fully above diagonal (square 128 tiles)
//   PVT    : truncate K loop at end of this M-tile (P@V causal structure)
#define EPI_STORE    0
#define EPI_BIAS     1
#define EPI_BIAS_RES 2
#define EPI_GELU     3
#define EPI_VT       4   /* bias + write transposed as V^T [b][d][s] */

template<int EPI, bool CAUSAL, bool PVT>
__global__ void __launch_bounds__(256, 2)
gemm_k(const float* __restrict__ A, const float* __restrict__ B,
       const float* __restrict__ bias, const float* __restrict__ res,
       float* __restrict__ C, int M, int N, int K,
       long long aB, long long bB, long long cB)
{
    const int bn = blockIdx.x, bm = blockIdx.y, bz = blockIdx.z;
    if (CAUSAL && bn > bm) return;
    A += (long long)bz * aB;
    B += (long long)bz * bB;
    C += (long long)bz * cB;

    extern __shared__ float sm[];

    const int tid  = threadIdx.x;
    const int lane = tid & 31;
    const int warp = tid >> 5;
    const int wm = (warp >> 1) * 32;   // 4 warps along M (32 rows each)
    const int wn = (warp & 1) * 64;    // 2 warps along N (64 cols each)
    const int g  = lane >> 2;
    const int tg = lane & 3;
    const int m0 = bm * MT, n0 = bn * NT;

    int ktiles = K / KT;
    if (PVT) { int kt2 = (bm + 1) * (MT / KT); if (kt2 < ktiles) ktiles = kt2; }

    float acc[2][8][4];
#pragma unroll
    for (int i = 0; i < 2; i++)
#pragma unroll
        for (int j = 0; j < 8; j++)
#pragma unroll
            for (int r = 0; r < 4; r++) acc[i][j][r] = 0.0f;

    // ldmatrix per-lane row/col selectors
    const int l8 = lane & 7, q = lane >> 3;
    const int a_row = (q & 1) * 8 + l8;
    const int a_col = (q >> 1) * 4;
    const int b_row = (q >> 1) * 8 + l8;
    const int b_col = (q & 1) * 4;

    auto issue = [&](int stage, int kt) {
        float* sA = sm + stage * STAGE_F;
        float* sB = sA + A_STAGE;
#pragma unroll
        for (int i = 0; i < 4; i++) {             // A: 128 rows x 8 chunks of 16B
            const int idx = tid + i * 256;
            const int row = idx >> 3, ch = idx & 7;
            cp16(&sA[row * ASTRIDE + ch * 4],
                 A + (size_t)(m0 + row) * K + kt * KT + ch * 4);
        }
#pragma unroll
        for (int i = 0; i < 4; i++) {             // B: 128 n-rows x 8 chunks
            const int idx = tid + i * 256;
            const int row = idx >> 3, ch = idx & 7;
            cp16(&sB[row * BSTRIDE + ch * 4],
                 B + (size_t)(n0 + row) * K + kt * KT + ch * 4);
        }
    };

    issue(0, 0); cp_commit();
    issue(1, 1); cp_commit();

    for (int kt = 0; kt < ktiles; kt++) {
        cp_wait<STAGES - 2>();
        __syncthreads();

        const int nkt = kt + STAGES - 1;
        if (nkt < ktiles) issue(nkt % STAGES, nkt);
        cp_commit();

        const float* sA = sm + (kt % STAGES) * STAGE_F;
        const float* sB = sA + A_STAGE;

#pragma unroll
        for (int ks = 0; ks < 4; ks++) {
            const int k0 = ks * 8;
            uint32_t af[2][4];
#pragma unroll
            for (int mi = 0; mi < 2; mi++)
                ldm4(af[mi], &sA[(wm + mi * 16 + a_row) * ASTRIDE + k0 + a_col]);
            uint32_t bf[8][2];
#pragma unroll
            for (int np = 0; np < 4; np++) {
                uint32_t r[4];
                ldm4(r, &sB[(wn + np * 16 + b_row) * BSTRIDE + k0 + b_col]);
                bf[2*np][0] = r[0]; bf[2*np][1] = r[1];
                bf[2*np+1][0] = r[2]; bf[2*np+1][1] = r[3];
            }
#pragma unroll
            for (int mi = 0; mi < 2; mi++)
#pragma unroll
                for (int ni = 0; ni < 8; ni++)
                    mma_tf32(acc[mi][ni], af[mi], bf[ni]);
        }
        __syncthreads();
    }

    if (EPI != EPI_VT) {
#pragma unroll
        for (int mi = 0; mi < 2; mi++) {
#pragma unroll
            for (int ni = 0; ni < 8; ni++) {
                const int r = m0 + wm + mi * 16 + g;
                const int c = n0 + wn + ni * 8 + tg * 2;
#pragma unroll
                for (int h = 0; h < 2; h++) {
                    const int rr = r + h * 8;
                    float v0 = acc[mi][ni][h * 2 + 0];
                    float v1 = acc[mi][ni][h * 2 + 1];
                    if (EPI == EPI_BIAS || EPI == EPI_BIAS_RES || EPI == EPI_GELU) {
                        v0 += bias[c]; v1 += bias[c + 1];
                    }
                    if (EPI == EPI_BIAS_RES) {
                        v0 += res[(size_t)rr * N + c];
                        v1 += res[(size_t)rr * N + c + 1];
                    }
                    if (EPI == EPI_GELU) { v0 = gelu_exact(v0); v1 = gelu_exact(v1); }
                    *(float2*)&C[(size_t)rr * N + c] = make_float2(v0, v1);
                }
            }
        }
    } else {
        // stage C tile transposed in smem as [n][m] then write V^T coalesced
        float* stg = sm;   // 128 x VT_STRIDE floats = 67584 B < SMEM_BYTES
#pragma unroll
        for (int mi = 0; mi < 2; mi++) {
#pragma unroll
            for (int ni = 0; ni < 8; ni++) {
                const int c = wn + ni * 8 + tg * 2;
#pragma unroll
                for (int h = 0; h < 2; h++) {
                    const int r = wm + mi * 16 + g + h * 8;
                    stg[(c    ) * VT_STRIDE + r] = acc[mi][ni][h * 2 + 0];
                    stg[(c + 1) * VT_STRIDE + r] = acc[mi][ni][h * 2 + 1];
                }
            }
        }
        __syncthreads();
        const int b = m0 >> 11, t0 = m0 & 2047;
        for (int nr = warp * 16; nr < warp * 16 + 16; nr++) {
            const int n = n0 + nr;
            const float bn_ = bias[n];
            float* dst = C + ((size_t)b * DIM + n) * SEQ + t0;
            const int m = lane * 4;
            float4 v = *(float4*)&stg[nr * VT_STRIDE + m];
            v.x += bn_; v.y += bn_; v.z += bn_; v.w += bn_;
            *(float4*)&dst[m] = v;
        }
    }
}

// ---------------- weight transpose: w[K][N] -> wt[N][K] ----------------
__global__ void wtrans_k(const float* __restrict__ w, float* __restrict__ wt, int Kd, int Nd)
{
    __shared__ float t[32][33];
    const int bx = blockIdx.x, by = blockIdx.y;
    const int tx = threadIdx.x, ty = threadIdx.y;   // (32,8)
#pragma unroll
    for (int j = 0; j < 4; j++)
        t[ty + j * 8][tx] = w[(size_t)(by * 32 + ty + j * 8) * Nd + bx * 32 + tx];
    __syncthreads();
#pragma unroll
    for (int j = 0; j < 4; j++)
        wt[(size_t)(bx * 32 + ty + j * 8) * Kd + by * 32 + tx] = t[tx][ty + j * 8];
}

// ---------------- RMSNorm ----------------
__global__ void __launch_bounds__(256, 1)
rmsnorm_k(const float* __restrict__ x, const float* __restrict__ w, float* __restrict__ o)
{
    __shared__ float red[8];
    __shared__ float bc;
    const int row = blockIdx.x;
    const size_t base = (size_t)row * DIM;
    const int tid = threadIdx.x, lane = tid & 31, warp = tid >> 5;

    float4 xv = ((const float4*)(x + base))[tid];
    float ss = xv.x * xv.x + xv.y * xv.y + xv.z * xv.z + xv.w * xv.w;
#pragma unroll
    for (int off = 16; off; off >>= 1) ss += __shfl_xor_sync(0xffffffffu, ss, off);
    if (lane == 0) red[warp] = ss;
    __syncthreads();
    if (tid == 0) {
        float t = 0.0f;
#pragma unroll
        for (int i = 0; i < 8; i++) t += red[i];
        bc = rsqrtf(t * (1.0f / DIM) + 1e-6f);
    }
    __syncthreads();
    const float inv = bc;
    float4 wv = ((const float4*)w)[tid];
    float4 ov;
    ov.x = xv.x * inv * wv.x; ov.y = xv.y * inv * wv.y;
    ov.z = xv.z * inv * wv.z; ov.w = xv.w * inv * wv.w;
    ((float4*)(o + base))[tid] = ov;
}

// ---------------- causal softmax (in place, zero-fill to 128-tile edge) ----------------
__global__ void __launch_bounds__(256, 1)
softmax_k(float* __restrict__ s)
{
    __shared__ float red[8];
    __shared__ float bc;
    const int t = blockIdx.x, b = blockIdx.y;
    float* row = s + ((size_t)b * SEQ + (size_t)t) * SEQ;
    const int L = t + 1;
    const int tid = threadIdx.x, lane = tid & 31, warp = tid >> 5;
    const float scale = 0.03125f;  // 1/sqrt(1024)

    float m = -3.4e38f;
    for (int j = tid; j < L; j += 256) m = fmaxf(m, row[j]);
#pragma unroll
    for (int off = 16; off; off >>= 1) m = fmaxf(m, __shfl_xor_sync(0xffffffffu, m, off));
    if (lane == 0) red[warp] = m;
    __syncthreads();
    if (tid == 0) {
        float mm = red[0];
#pragma unroll
        for (int i = 1; i < 8; i++) mm = fmaxf(mm, red[i]);
        bc = mm;
    }
    __syncthreads();
    const float mm = bc;
    __syncthreads();

    float sum = 0.0f;
    for (int j = tid; j < L; j += 256) {
        float e = expf((row[j] - mm) * scale);
        row[j] = e;
        sum += e;
    }
#pragma unroll
    for (int off = 16; off; off >>= 1) sum += __shfl_xor_sync(0xffffffffu, sum, off);
    if (lane == 0) red[warp] = sum;
    __syncthreads();
    if (tid == 0) {
        float ss = 0.0f;
#pragma unroll
        for (int i = 0; i < 8; i++) ss += red[i];
        bc = 1.0f / ss;
    }
    __syncthreads();
    const float inv = bc;
    for (int j = tid; j < L; j += 256) row[j] *= inv;

    const int jend = ((t >> 7) + 1) << 7;
    for (int j = L + tid; j < jend; j += 256) row[j] = 0.0f;
}

// ---------------- launch ----------------
extern "C" void kernel_launch(void* const* d_in, const int* in_sizes, int n_in,
                              void* d_out, int out_size)
{
    (void)in_sizes; (void)n_in; (void)out_size;
    const float* x   = (const float*)d_in[0];
    const float* anw = (const float*)d_in[1];
    const float* mnw = (const float*)d_in[2];
    const float* wq  = (const float*)d_in[3];
    const float* bq  = (const float*)d_in[4];
    const float* wk  = (const float*)d_in[5];
    const float* bk  = (const float*)d_in[6];
    const float* wv  = (const float*)d_in[7];
    const float* bv  = (const float*)d_in[8];
    const float* wo  = (const float*)d_in[9];
    const float* bo  = (const float*)d_in[10];
    const float* w1  = (const float*)d_in[11];
    const float* b1  = (const float*)d_in[12];
    const float* w2  = (const float*)d_in[13];
    const float* b2  = (const float*)d_in[14];
    float* out = (float*)d_out;

    float *xn, *q, *k, *vt, *attn, *xmid, *h1, *sc;
    float *wqt, *wkt, *wvt, *wot, *w1t, *w2t;
    cudaGetSymbolAddress((void**)&xn,   g_xn);
    cudaGetSymbolAddress((void**)&q,    g_q);
    cudaGetSymbolAddress((void**)&k,    g_k);
    cudaGetSymbolAddress((void**)&vt,   g_vt);
    cudaGetSymbolAddress((void**)&attn, g_attn);
    cudaGetSymbolAddress((void**)&xmid, g_xmid);
    cudaGetSymbolAddress((void**)&h1,   g_h1);
    cudaGetSymbolAddress((void**)&sc,   g_sc);
    cudaGetSymbolAddress((void**)&wqt,  g_wqt);
    cudaGetSymbolAddress((void**)&wkt,  g_wkt);
    cudaGetSymbolAddress((void**)&wvt,  g_wvt);
    cudaGetSymbolAddress((void**)&wot,  g_wot);
    cudaGetSymbolAddress((void**)&w1t,  g_w1t);
    cudaGetSymbolAddress((void**)&w2t,  g_w2t);

    cudaFuncSetAttribute(gemm_k<EPI_BIAS,     false, false>,
                         cudaFuncAttributeMaxDynamicSharedMemorySize, SMEM_BYTES);
    cudaFuncSetAttribute(gemm_k<EPI_VT,       false, false>,
                         cudaFuncAttributeMaxDynamicSharedMemorySize, SMEM_BYTES);
    cudaFuncSetAttribute(gemm_k<EPI_STORE,    true,  false>,
                         cudaFuncAttributeMaxDynamicSharedMemorySize, SMEM_BYTES);
    cudaFuncSetAttribute(gemm_k<EPI_STORE,    false, true >,
                         cudaFuncAttributeMaxDynamicSharedMemorySize, SMEM_BYTES);
    cudaFuncSetAttribute(gemm_k<EPI_BIAS_RES, false, false>,
                         cudaFuncAttributeMaxDynamicSharedMemorySize, SMEM_BYTES);
    cudaFuncSetAttribute(gemm_k<EPI_GELU,     false, false>,
                         cudaFuncAttributeMaxDynamicSharedMemorySize, SMEM_BYTES);

    const long long SD = (long long)SEQ * DIM;
    const long long SS = (long long)SEQ * SEQ;
    const dim3 wb(32, 8);

    // 0) transpose weights to [N][K]
    wtrans_k<<<dim3(DIM/32, DIM/32), wb>>>(wq, wqt, DIM, DIM);
    wtrans_k<<<dim3(DIM/32, DIM/32), wb>>>(wk, wkt, DIM, DIM);
    wtrans_k<<<dim3(DIM/32, DIM/32), wb>>>(wv, wvt, DIM, DIM);
    wtrans_k<<<dim3(DIM/32, DIM/32), wb>>>(wo, wot, DIM, DIM);
    wtrans_k<<<dim3(HID/32, DIM/32), wb>>>(w1, w1t, DIM, HID);
    wtrans_k<<<dim3(DIM/32, HID/32), wb>>>(w2, w2t, HID, DIM);

    // 1) xn = rmsnorm(x) * attn_norm_w
    rmsnorm_k<<<ROWS, 256>>>(x, anw, xn);

    // 2) Q, K, V (V written transposed as V^T)
    gemm_k<EPI_BIAS, false, false><<<dim3(DIM/NT, ROWS/MT, 1), 256, SMEM_BYTES>>>(
        xn, wqt, bq, nullptr, q, ROWS, DIM, DIM, 0, 0, 0);
    gemm_k<EPI_BIAS, false, false><<<dim3(DIM/NT, ROWS/MT, 1), 256, SMEM_BYTES>>>(
        xn, wkt, bk, nullptr, k, ROWS, DIM, DIM, 0, 0, 0);
    gemm_k<EPI_VT, false, false><<<dim3(DIM/NT, ROWS/MT, 1), 256, SMEM_BYTES>>>(
        xn, wvt, bv, nullptr, vt, ROWS, DIM, DIM, 0, 0, 0);

    // 3) scores = Q @ K^T (per batch, causal block-skip)
    gemm_k<EPI_STORE, true, false><<<dim3(SEQ/NT, SEQ/MT, BATCH), 256, SMEM_BYTES>>>(
        q, k, nullptr, nullptr, sc, SEQ, SEQ, DIM, SD, SD, SS);

    // 4) causal softmax
    softmax_k<<<dim3(SEQ, BATCH), 256>>>(sc);

    // 5) attn = P @ V  (B = V^T [d][s], K loop truncated)
    gemm_k<EPI_STORE, false, true><<<dim3(DIM/NT, SEQ/MT, BATCH), 256, SMEM_BYTES>>>(
        sc, vt, nullptr, nullptr, attn, SEQ, DIM, SEQ, SS, SD, SD);

    // 6) xmid = x + attn @ wo + bo
    gemm_k<EPI_BIAS_RES, false, false><<<dim3(DIM/NT, ROWS/MT, 1), 256, SMEM_BYTES>>>(
        attn, wot, bo, x, xmid, ROWS, DIM, DIM, 0, 0, 0);

    // 7) h = rmsnorm(xmid) * mlp_norm_w
    rmsnorm_k<<<ROWS, 256>>>(xmid, mnw, xn);

    // 8) h1 = gelu(h @ w1 + b1)
    gemm_k<EPI_GELU, false, false><<<dim3(HID/NT, ROWS/MT, 1), 256, SMEM_BYTES>>>(
        xn, w1t, b1, nullptr, h1, ROWS, HID, DIM, 0, 0, 0);

    // 9) out = xmid + h1 @ w2 + b2
    gemm_k<EPI_BIAS_RES, false, false><<<dim3(DIM/NT, ROWS/MT, 1), 256, SMEM_BYTES>>>(
        h1, w2t, b2, xmid, out, ROWS, DIM, HID, 0, 0, 0);
}

// round 6
// speedup vs baseline: 1.4882x; 1.0177x over previous
#include <cuda_runtime.h>
#include <cstdint>
#include <math.h>

#define BATCH 8
#define SEQ   2048
#define DIM   1024
#define HID   4096
#define ROWS  (BATCH*SEQ)   /* 16384 */

// GEMM tiling: CTA 128x128x32, 4 warps of 64x64, 2 CTAs/SM
#define MT 128
#define NT 128
#define KT 32
#define CTHREADS 128
#define STAGES 3
#define ASTRIDE 36
#define BSTRIDE 36
#define A_STAGE (MT*ASTRIDE)            /* 4608 floats */
#define B_STAGE (NT*BSTRIDE)            /* 4608 floats */
#define STAGE_F (A_STAGE + B_STAGE)     /* 9216 floats */
#define SMEM_BYTES (STAGES*STAGE_F*4)   /* 110592 bytes -> 2 CTAs/SM */
#define VT_STRIDE 132                   /* V^T epilogue staging stride */

// ---------------- scratch (allocation-free: __device__ globals) ----------------
static __device__ float g_xn  [(size_t)ROWS*DIM];
static __device__ float g_q   [(size_t)ROWS*DIM];
static __device__ float g_k   [(size_t)ROWS*DIM];
static __device__ float g_vt  [(size_t)ROWS*DIM];     // V^T: [b][d][s]
static __device__ float g_attn[(size_t)ROWS*DIM];
static __device__ float g_xmid[(size_t)ROWS*DIM];
static __device__ float g_h1  [(size_t)ROWS*HID];
static __device__ float g_sc  [(size_t)BATCH*SEQ*SEQ];
// weights transposed to [N][K]
static __device__ float g_wqt [(size_t)DIM*DIM];
static __device__ float g_wkt [(size_t)DIM*DIM];
static __device__ float g_wvt [(size_t)DIM*DIM];
static __device__ float g_wot [(size_t)DIM*DIM];
static __device__ float g_w1t [(size_t)HID*DIM];
static __device__ float g_w2t [(size_t)DIM*HID];

// ---------------- helpers ----------------
__device__ __forceinline__ float gelu_exact(float x) {
    return 0.5f * x * (1.0f + erff(x * 0.70710678118654752440f));
}

__device__ __forceinline__ void mma_tf32(float d[4], const uint32_t a[4], const uint32_t b[2]) {
    asm volatile(
        "mma.sync.aligned.m16n8k8.row.col.f32.tf32.tf32.f32 "
        "{%0,%1,%2,%3}, {%4,%5,%6,%7}, {%8,%9}, {%0,%1,%2,%3};\n"
        : "+f"(d[0]), "+f"(d[1]), "+f"(d[2]), "+f"(d[3])
        : "r"(a[0]), "r"(a[1]), "r"(a[2]), "r"(a[3]), "r"(b[0]), "r"(b[1]));
}

__device__ __forceinline__ void ldm4(uint32_t r[4], const float* p) {
    uint32_t a = (uint32_t)__cvta_generic_to_shared(p);
    asm volatile("ldmatrix.sync.aligned.m8n8.x4.shared.b16 {%0,%1,%2,%3}, [%4];\n"
                 : "=r"(r[0]), "=r"(r[1]), "=r"(r[2]), "=r"(r[3]) : "r"(a));
}

__device__ __forceinline__ void cp16(float* smem, const float* gmem) {
    uint32_t s = (uint32_t)__cvta_generic_to_shared(smem);
    asm volatile("cp.async.cg.shared.global [%0], [%1], 16;\n" :: "r"(s), "l"(gmem));
}
__device__ __forceinline__ void cp_commit() { asm volatile("cp.async.commit_group;\n"); }
template<int N>
__device__ __forceinline__ void cp_wait() { asm volatile("cp.async.wait_group %0;\n" :: "n"(N)); }

// ---------------- GEMM ----------------
// C[M,N] = A[M,K] @ B^T + epi, where B is stored [N][K] (k-major rows).
//   CAUSAL : skip CTA if N-tile fully above diagonal (square 128 tiles)
//   PVT    : truncate K loop at end of this M-tile (P@V causal structure)
#define EPI_STORE    0
#define EPI_BIAS     1
#define EPI_BIAS_RES 2
#define EPI_GELU     3
#define EPI_VT       4   /* bias + write transposed as V^T [b][d][s] */

template<int EPI, bool CAUSAL, bool PVT>
__global__ void __launch_bounds__(CTHREADS, 2)
gemm_k(const float* __restrict__ A, const float* __restrict__ B,
       const float* __restrict__ bias, const float* __restrict__ res,
       float* __restrict__ C, int M, int N, int K,
       long long aB, long long bB, long long cB)
{
    const int bn = blockIdx.x, bm = blockIdx.y, bz = blockIdx.z;
    if (CAUSAL && bn > bm) return;
    A += (long long)bz * aB;
    B += (long long)bz * bB;
    C += (long long)bz * cB;

    extern __shared__ float sm[];

    const int tid  = threadIdx.x;
    const int lane = tid & 31;
    const int warp = tid >> 5;
    const int wm = (warp >> 1) * 64;   // 2 warps along M (64 rows each)
    const int wn = (warp & 1) * 64;    // 2 warps along N (64 cols each)
    const int g  = lane >> 2;
    const int tg = lane & 3;
    const int m0 = bm * MT, n0 = bn * NT;

    int ktiles = K / KT;
    if (PVT) { int kt2 = (bm + 1) * (MT / KT); if (kt2 < ktiles) ktiles = kt2; }

    float acc[4][8][4];
#pragma unroll
    for (int i = 0; i < 4; i++)
#pragma unroll
        for (int j = 0; j < 8; j++)
#pragma unroll
            for (int r = 0; r < 4; r++) acc[i][j][r] = 0.0f;

    // ldmatrix per-lane row/col selectors
    const int l8 = lane & 7, q = lane >> 3;
    const int a_row = (q & 1) * 8 + l8;
    const int a_col = (q >> 1) * 4;
    const int b_row = (q >> 1) * 8 + l8;
    const int b_col = (q & 1) * 4;

    auto issue = [&](int stage, int kt) {
        float* sA = sm + stage * STAGE_F;
        float* sB = sA + A_STAGE;
#pragma unroll
        for (int i = 0; i < 8; i++) {             // A: 128 rows x 8 chunks of 16B
            const int idx = tid + i * CTHREADS;
            const int row = idx >> 3, ch = idx & 7;
            cp16(&sA[row * ASTRIDE + ch * 4],
                 A + (size_t)(m0 + row) * K + kt * KT + ch * 4);
        }
#pragma unroll
        for (int i = 0; i < 8; i++) {             // B: 128 n-rows x 8 chunks
            const int idx = tid + i * CTHREADS;
            const int row = idx >> 3, ch = idx & 7;
            cp16(&sB[row * BSTRIDE + ch * 4],
                 B + (size_t)(n0 + row) * K + kt * KT + ch * 4);
        }
    };

    issue(0, 0); cp_commit();
    issue(1, 1); cp_commit();

    for (int kt = 0; kt < ktiles; kt++) {
        cp_wait<STAGES - 2>();
        __syncthreads();

        const int nkt = kt + STAGES - 1;
        if (nkt < ktiles) issue(nkt % STAGES, nkt);
        cp_commit();

        const float* sA = sm + (kt % STAGES) * STAGE_F;
        const float* sB = sA + A_STAGE;

#pragma unroll
        for (int ks = 0; ks < 4; ks++) {
            const int k0 = ks * 8;
            uint32_t af[4][4];
#pragma unroll
            for (int mi = 0; mi < 4; mi++)
                ldm4(af[mi], &sA[(wm + mi * 16 + a_row) * ASTRIDE + k0 + a_col]);
            uint32_t bf[8][2];
#pragma unroll
            for (int np = 0; np < 4; np++) {
                uint32_t r[4];
                ldm4(r, &sB[(wn + np * 16 + b_row) * BSTRIDE + k0 + b_col]);
                bf[2*np][0] = r[0]; bf[2*np][1] = r[1];
                bf[2*np+1][0] = r[2]; bf[2*np+1][1] = r[3];
            }
#pragma unroll
            for (int mi = 0; mi < 4; mi++)
#pragma unroll
                for (int ni = 0; ni < 8; ni++)
                    mma_tf32(acc[mi][ni], af[mi], bf[ni]);
        }
        __syncthreads();
    }

    if (EPI != EPI_VT) {
#pragma unroll
        for (int mi = 0; mi < 4; mi++) {
#pragma unroll
            for (int ni = 0; ni < 8; ni++) {
                const int r = m0 + wm + mi * 16 + g;
                const int c = n0 + wn + ni * 8 + tg * 2;
#pragma unroll
                for (int h = 0; h < 2; h++) {
                    const int rr = r + h * 8;
                    float v0 = acc[mi][ni][h * 2 + 0];
                    float v1 = acc[mi][ni][h * 2 + 1];
                    if (EPI == EPI_BIAS || EPI == EPI_BIAS_RES || EPI == EPI_GELU) {
                        v0 += bias[c]; v1 += bias[c + 1];
                    }
                    if (EPI == EPI_BIAS_RES) {
                        v0 += res[(size_t)rr * N + c];
                        v1 += res[(size_t)rr * N + c + 1];
                    }
                    if (EPI == EPI_GELU) { v0 = gelu_exact(v0); v1 = gelu_exact(v1); }
                    *(float2*)&C[(size_t)rr * N + c] = make_float2(v0, v1);
                }
            }
        }
    } else {
        // stage C tile transposed in smem as [n][m] then write V^T coalesced
        float* stg = sm;   // 128 x VT_STRIDE floats = 67584 B < SMEM_BYTES
#pragma unroll
        for (int mi = 0; mi < 4; mi++) {
#pragma unroll
            for (int ni = 0; ni < 8; ni++) {
                const int c = wn + ni * 8 + tg * 2;
#pragma unroll
                for (int h = 0; h < 2; h++) {
                    const int r = wm + mi * 16 + g + h * 8;
                    stg[(c    ) * VT_STRIDE + r] = acc[mi][ni][h * 2 + 0];
                    stg[(c + 1) * VT_STRIDE + r] = acc[mi][ni][h * 2 + 1];
                }
            }
        }
        __syncthreads();
        const int b = m0 >> 11, t0 = m0 & 2047;
        for (int nr = warp * 32; nr < warp * 32 + 32; nr++) {
            const int n = n0 + nr;
            const float bn_ = bias[n];
            float* dst = C + ((size_t)b * DIM + n) * SEQ + t0;
            const int m = lane * 4;
            float4 v = *(float4*)&stg[nr * VT_STRIDE + m];
            v.x += bn_; v.y += bn_; v.z += bn_; v.w += bn_;
            *(float4*)&dst[m] = v;
        }
    }
}

// ---------------- weight transpose: w[K][N] -> wt[N][K] ----------------
__global__ void wtrans_k(const float* __restrict__ w, float* __restrict__ wt, int Kd, int Nd)
{
    __shared__ float t[32][33];
    const int bx = blockIdx.x, by = blockIdx.y;
    const int tx = threadIdx.x, ty = threadIdx.y;   // (32,8)
#pragma unroll
    for (int j = 0; j < 4; j++)
        t[ty + j * 8][tx] = w[(size_t)(by * 32 + ty + j * 8) * Nd + bx * 32 + tx];
    __syncthreads();
#pragma unroll
    for (int j = 0; j < 4; j++)
        wt[(size_t)(bx * 32 + ty + j * 8) * Kd + by * 32 + tx] = t[tx][ty + j * 8];
}

// ---------------- RMSNorm ----------------
__global__ void __launch_bounds__(256, 1)
rmsnorm_k(const float* __restrict__ x, const float* __restrict__ w, float* __restrict__ o)
{
    __shared__ float red[8];
    __shared__ float bc;
    const int row = blockIdx.x;
    const size_t base = (size_t)row * DIM;
    const int tid = threadIdx.x, lane = tid & 31, warp = tid >> 5;

    float4 xv = ((const float4*)(x + base))[tid];
    float ss = xv.x * xv.x + xv.y * xv.y + xv.z * xv.z + xv.w * xv.w;
#pragma unroll
    for (int off = 16; off; off >>= 1) ss += __shfl_xor_sync(0xffffffffu, ss, off);
    if (lane == 0) red[warp] = ss;
    __syncthreads();
    if (tid == 0) {
        float t = 0.0f;
#pragma unroll
        for (int i = 0; i < 8; i++) t += red[i];
        bc = rsqrtf(t * (1.0f / DIM) + 1e-6f);
    }
    __syncthreads();
    const float inv = bc;
    float4 wv = ((const float4*)w)[tid];
    float4 ov;
    ov.x = xv.x * inv * wv.x; ov.y = xv.y * inv * wv.y;
    ov.z = xv.z * inv * wv.z; ov.w = xv.w * inv * wv.w;
    ((float4*)(o + base))[tid] = ov;
}

// ---------------- causal softmax (in place, zero-fill to 128-tile edge) ----------------
__global__ void __launch_bounds__(256, 1)
softmax_k(float* __restrict__ s)
{
    __shared__ float red[8];
    __shared__ float bc;
    const int t = blockIdx.x, b = blockIdx.y;
    float* row = s + ((size_t)b * SEQ + (size_t)t) * SEQ;
    const int L = t + 1;
    const int tid = threadIdx.x, lane = tid & 31, warp = tid >> 5;
    const float scale = 0.03125f;  // 1/sqrt(1024)

    float m = -3.4e38f;
    for (int j = tid; j < L; j += 256) m = fmaxf(m, row[j]);
#pragma unroll
    for (int off = 16; off; off >>= 1) m = fmaxf(m, __shfl_xor_sync(0xffffffffu, m, off));
    if (lane == 0) red[warp] = m;
    __syncthreads();
    if (tid == 0) {
        float mm = red[0];
#pragma unroll
        for (int i = 1; i < 8; i++) mm = fmaxf(mm, red[i]);
        bc = mm;
    }
    __syncthreads();
    const float mm = bc;
    __syncthreads();

    float sum = 0.0f;
    for (int j = tid; j < L; j += 256) {
        float e = expf((row[j] - mm) * scale);
        row[j] = e;
        sum += e;
    }
#pragma unroll
    for (int off = 16; off; off >>= 1) sum += __shfl_xor_sync(0xffffffffu, sum, off);
    if (lane == 0) red[warp] = sum;
    __syncthreads();
    if (tid == 0) {
        float ss = 0.0f;
#pragma unroll
        for (int i = 0; i < 8; i++) ss += red[i];
        bc = 1.0f / ss;
    }
    __syncthreads();
    const float inv = bc;
    for (int j = tid; j < L; j += 256) row[j] *= inv;

    const int jend = ((t >> 7) + 1) << 7;
    for (int j = L + tid; j < jend; j += 256) row[j] = 0.0f;
}

// ---------------- launch ----------------
extern "C" void kernel_launch(void* const* d_in, const int* in_sizes, int n_in,
                              void* d_out, int out_size)
{
    (void)in_sizes; (void)n_in; (void)out_size;
    const float* x   = (const float*)d_in[0];
    const float* anw = (const float*)d_in[1];
    const float* mnw = (const float*)d_in[2];
    const float* wq  = (const float*)d_in[3];
    const float* bq  = (const float*)d_in[4];
    const float* wk  = (const float*)d_in[5];
    const float* bk  = (const float*)d_in[6];
    const float* wv  = (const float*)d_in[7];
    const float* bv  = (const float*)d_in[8];
    const float* wo  = (const float*)d_in[9];
    const float* bo  = (const float*)d_in[10];
    const float* w1  = (const float*)d_in[11];
    const float* b1  = (const float*)d_in[12];
    const float* w2  = (const float*)d_in[13];
    const float* b2  = (const float*)d_in[14];
    float* out = (float*)d_out;

    float *xn, *q, *k, *vt, *attn, *xmid, *h1, *sc;
    float *wqt, *wkt, *wvt, *wot, *w1t, *w2t;
    cudaGetSymbolAddress((void**)&xn,   g_xn);
    cudaGetSymbolAddress((void**)&q,    g_q);
    cudaGetSymbolAddress((void**)&k,    g_k);
    cudaGetSymbolAddress((void**)&vt,   g_vt);
    cudaGetSymbolAddress((void**)&attn, g_attn);
    cudaGetSymbolAddress((void**)&xmid, g_xmid);
    cudaGetSymbolAddress((void**)&h1,   g_h1);
    cudaGetSymbolAddress((void**)&sc,   g_sc);
    cudaGetSymbolAddress((void**)&wqt,  g_wqt);
    cudaGetSymbolAddress((void**)&wkt,  g_wkt);
    cudaGetSymbolAddress((void**)&wvt,  g_wvt);
    cudaGetSymbolAddress((void**)&wot,  g_wot);
    cudaGetSymbolAddress((void**)&w1t,  g_w1t);
    cudaGetSymbolAddress((void**)&w2t,  g_w2t);

    cudaFuncSetAttribute(gemm_k<EPI_BIAS,     false, false>,
                         cudaFuncAttributeMaxDynamicSharedMemorySize, SMEM_BYTES);
    cudaFuncSetAttribute(gemm_k<EPI_VT,       false, false>,
                         cudaFuncAttributeMaxDynamicSharedMemorySize, SMEM_BYTES);
    cudaFuncSetAttribute(gemm_k<EPI_STORE,    true,  false>,
                         cudaFuncAttributeMaxDynamicSharedMemorySize, SMEM_BYTES);
    cudaFuncSetAttribute(gemm_k<EPI_STORE,    false, true >,
                         cudaFuncAttributeMaxDynamicSharedMemorySize, SMEM_BYTES);
    cudaFuncSetAttribute(gemm_k<EPI_BIAS_RES, false, false>,
                         cudaFuncAttributeMaxDynamicSharedMemorySize, SMEM_BYTES);
    cudaFuncSetAttribute(gemm_k<EPI_GELU,     false, false>,
                         cudaFuncAttributeMaxDynamicSharedMemorySize, SMEM_BYTES);

    const long long SD = (long long)SEQ * DIM;
    const long long SS = (long long)SEQ * SEQ;
    const dim3 wb(32, 8);

    // 0) transpose weights to [N][K]
    wtrans_k<<<dim3(DIM/32, DIM/32), wb>>>(wq, wqt, DIM, DIM);
    wtrans_k<<<dim3(DIM/32, DIM/32), wb>>>(wk, wkt, DIM, DIM);
    wtrans_k<<<dim3(DIM/32, DIM/32), wb>>>(wv, wvt, DIM, DIM);
    wtrans_k<<<dim3(DIM/32, DIM/32), wb>>>(wo, wot, DIM, DIM);
    wtrans_k<<<dim3(HID/32, DIM/32), wb>>>(w1, w1t, DIM, HID);
    wtrans_k<<<dim3(DIM/32, HID/32), wb>>>(w2, w2t, HID, DIM);

    // 1) xn = rmsnorm(x) * attn_norm_w
    rmsnorm_k<<<ROWS, 256>>>(x, anw, xn);

    // 2) Q, K, V (V written transposed as V^T)
    gemm_k<EPI_BIAS, false, false><<<dim3(DIM/NT, ROWS/MT, 1), CTHREADS, SMEM_BYTES>>>(
        xn, wqt, bq, nullptr, q, ROWS, DIM, DIM, 0, 0, 0);
    gemm_k<EPI_BIAS, false, false><<<dim3(DIM/NT, ROWS/MT, 1), CTHREADS, SMEM_BYTES>>>(
        xn, wkt, bk, nullptr, k, ROWS, DIM, DIM, 0, 0, 0);
    gemm_k<EPI_VT, false, false><<<dim3(DIM/NT, ROWS/MT, 1), CTHREADS, SMEM_BYTES>>>(
        xn, wvt, bv, nullptr, vt, ROWS, DIM, DIM, 0, 0, 0);

    // 3) scores = Q @ K^T (per batch, causal block-skip)
    gemm_k<EPI_STORE, true, false><<<dim3(SEQ/NT, SEQ/MT, BATCH), CTHREADS, SMEM_BYTES>>>(
        q, k, nullptr, nullptr, sc, SEQ, SEQ, DIM, SD, SD, SS);

    // 4) causal softmax
    softmax_k<<<dim3(SEQ, BATCH), 256>>>(sc);

    // 5) attn = P @ V  (B = V^T [d][s], K loop truncated)
    gemm_k<EPI_STORE, false, true><<<dim3(DIM/NT, SEQ/MT, BATCH), CTHREADS, SMEM_BYTES>>>(
        sc, vt, nullptr, nullptr, attn, SEQ, DIM, SEQ, SS, SD, SD);

    // 6) xmid = x + attn @ wo + bo
    gemm_k<EPI_BIAS_RES, false, false><<<dim3(DIM/NT, ROWS/MT, 1), CTHREADS, SMEM_BYTES>>>(
        attn, wot, bo, x, xmid, ROWS, DIM, DIM, 0, 0, 0);

    // 7) h = rmsnorm(xmid) * mlp_norm_w
    rmsnorm_k<<<ROWS, 256>>>(xmid, mnw, xn);

    // 8) h1 = gelu(h @ w1 + b1)
    gemm_k<EPI_GELU, false, false><<<dim3(HID/NT, ROWS/MT, 1), CTHREADS, SMEM_BYTES>>>(
        xn, w1t, b1, nullptr, h1, ROWS, HID, DIM, 0, 0, 0);

    // 9) out = xmid + h1 @ w2 + b2
    gemm_k<EPI_BIAS_RES, false, false><<<dim3(DIM/NT, ROWS/MT, 1), CTHREADS, SMEM_BYTES>>>(
        h1, w2t, b2, xmid, out, ROWS, DIM, HID, 0, 0, 0);
}

// round 7
// speedup vs baseline: 2.3855x; 1.6030x over previous
#include <cuda_runtime.h>
#include <cuda_fp16.h>
#include <cstdint>
#include <math.h>

#define BATCH 8
#define SEQ   2048
#define DIM   1024
#define HID   4096
#define ROWS  (BATCH*SEQ)   /* 16384 */

// GEMM tiling: CTA 128x128x32, 4 warps of 64x64, fp16 operands, 2 CTAs/SM
#define MT 128
#define NT 128
#define KT 32
#define CTHREADS 128
#define STAGES 4
#define ASTRIDE 40                       /* halves per A-row (32 + 8 pad) */
#define BSTRIDE 40
#define A_STAGE (MT*ASTRIDE)             /* 5120 halves */
#define B_STAGE (NT*BSTRIDE)             /* 5120 halves */
#define STAGE_H (A_STAGE + B_STAGE)      /* 10240 halves = 20480 B */
#define SMEM_BYTES (STAGES*STAGE_H*2)    /* 81920 B -> 2 CTAs/SM */
#define VT_STRIDE 136                    /* halves, V^T staging */

// ---------------- scratch (allocation-free: __device__ globals) ----------------
static __device__ __half g_xn  [(size_t)ROWS*DIM];
static __device__ __half g_q   [(size_t)ROWS*DIM];
static __device__ __half g_k   [(size_t)ROWS*DIM];
static __device__ __half g_vt  [(size_t)ROWS*DIM];     // V^T: [b][d][s]
static __device__ __half g_attn[(size_t)ROWS*DIM];
static __device__ __half g_h1  [(size_t)ROWS*HID];
static __device__ __half g_p   [(size_t)BATCH*SEQ*SEQ];
static __device__ float  g_sc  [(size_t)BATCH*SEQ*SEQ];
static __device__ float  g_xmid[(size_t)ROWS*DIM];
// weights transposed to [N][K], fp16
static __device__ __half g_wqt [(size_t)DIM*DIM];
static __device__ __half g_wkt [(size_t)DIM*DIM];
static __device__ __half g_wvt [(size_t)DIM*DIM];
static __device__ __half g_wot [(size_t)DIM*DIM];
static __device__ __half g_w1t [(size_t)HID*DIM];
static __device__ __half g_w2t [(size_t)DIM*HID];

// ---------------- helpers ----------------
__device__ __forceinline__ float gelu_exact(float x) {
    return 0.5f * x * (1.0f + erff(x * 0.70710678118654752440f));
}

__device__ __forceinline__ void mma_f16(float d[4], const uint32_t a[4], const uint32_t b[2]) {
    asm volatile(
        "mma.sync.aligned.m16n8k16.row.col.f32.f16.f16.f32 "
        "{%0,%1,%2,%3}, {%4,%5,%6,%7}, {%8,%9}, {%0,%1,%2,%3};\n"
        : "+f"(d[0]), "+f"(d[1]), "+f"(d[2]), "+f"(d[3])
        : "r"(a[0]), "r"(a[1]), "r"(a[2]), "r"(a[3]), "r"(b[0]), "r"(b[1]));
}

__device__ __forceinline__ void ldm4(uint32_t r[4], const __half* p) {
    uint32_t a = (uint32_t)__cvta_generic_to_shared(p);
    asm volatile("ldmatrix.sync.aligned.m8n8.x4.shared.b16 {%0,%1,%2,%3}, [%4];\n"
                 : "=r"(r[0]), "=r"(r[1]), "=r"(r[2]), "=r"(r[3]) : "r"(a));
}

__device__ __forceinline__ void cp16(__half* smem, const __half* gmem) {
    uint32_t s = (uint32_t)__cvta_generic_to_shared(smem);
    asm volatile("cp.async.cg.shared.global [%0], [%1], 16;\n" :: "r"(s), "l"(gmem));
}
__device__ __forceinline__ void cp_commit() { asm volatile("cp.async.commit_group;\n"); }
template<int N>
__device__ __forceinline__ void cp_wait() { asm volatile("cp.async.wait_group %0;\n" :: "n"(N)); }

// ---------------- GEMM ----------------
// C[M,N] = A[M,K] @ B^T + epi; A fp16 [M][K], B fp16 [N][K] k-major.
//   CAUSAL : skip CTA if N-tile fully above diagonal (square 128 tiles)
//   PVT    : truncate K loop at end of this M-tile (P@V causal structure)
#define EPI_STORE_F    0   /* scores: fp32 store */
#define EPI_BIAS_H     1   /* q,k: bias, fp16 store */
#define EPI_BIAS_RES_F 2   /* xmid/out: bias+residual, fp32 store */
#define EPI_GELU_H     3   /* h1: gelu(bias), fp16 store */
#define EPI_VT_H       4   /* v: bias, fp16 store transposed as V^T */
#define EPI_STORE_H    5   /* attn: fp16 store */

template<int EPI, bool CAUSAL, bool PVT>
__global__ void __launch_bounds__(CTHREADS, 2)
gemm_k(const __half* __restrict__ A, const __half* __restrict__ B,
       const float* __restrict__ bias, const float* __restrict__ res,
       float* __restrict__ Cf, __half* __restrict__ Ch,
       int M, int N, int K,
       long long aB, long long bB, long long cB)
{
    const int bn = blockIdx.x, bm = blockIdx.y, bz = blockIdx.z;
    if (CAUSAL && bn > bm) return;
    A += (long long)bz * aB;
    B += (long long)bz * bB;

    extern __shared__ __half sm[];

    const int tid  = threadIdx.x;
    const int lane = tid & 31;
    const int warp = tid >> 5;
    const int wm = (warp >> 1) * 64;   // 2 warps along M (64 rows each)
    const int wn = (warp & 1) * 64;    // 2 warps along N (64 cols each)
    const int g  = lane >> 2;
    const int tg = lane & 3;
    const int m0 = bm * MT, n0 = bn * NT;

    int ktiles = K / KT;
    if (PVT) { int kt2 = (bm + 1) * (MT / KT); if (kt2 < ktiles) ktiles = kt2; }

    float acc[4][8][4];
#pragma unroll
    for (int i = 0; i < 4; i++)
#pragma unroll
        for (int j = 0; j < 8; j++)
#pragma unroll
            for (int r = 0; r < 4; r++) acc[i][j][r] = 0.0f;

    // ldmatrix per-lane selectors (halves)
    const int l8 = lane & 7, q = lane >> 3;
    const int a_row = (q & 1) * 8 + l8;      // A: m0-7/m8-15 x k0-7 / k8-15
    const int a_col = (q >> 1) * 8;
    const int b_row = (q >> 1) * 8 + l8;     // B: n0-7 x k0-7,k8-15 then n8-15
    const int b_col = (q & 1) * 8;

    auto issue = [&](int stage, int kt) {
        __half* sA = sm + stage * STAGE_H;
        __half* sB = sA + A_STAGE;
#pragma unroll
        for (int i = 0; i < 4; i++) {             // A: 128 rows x 4 chunks of 16B
            const int idx = tid + i * CTHREADS;
            const int row = idx >> 2, ch = idx & 3;
            cp16(&sA[row * ASTRIDE + ch * 8],
                 A + (size_t)(m0 + row) * K + kt * KT + ch * 8);
        }
#pragma unroll
        for (int i = 0; i < 4; i++) {             // B: 128 n-rows x 4 chunks
            const int idx = tid + i * CTHREADS;
            const int row = idx >> 2, ch = idx & 3;
            cp16(&sB[row * BSTRIDE + ch * 8],
                 B + (size_t)(n0 + row) * K + kt * KT + ch * 8);
        }
    };

#pragma unroll
    for (int s = 0; s < STAGES - 1; s++) {
        if (s < ktiles) issue(s, s);
        cp_commit();
    }

    for (int kt = 0; kt < ktiles; kt++) {
        cp_wait<STAGES - 2>();
        __syncthreads();

        const int nkt = kt + STAGES - 1;
        if (nkt < ktiles) issue(nkt % STAGES, nkt);
        cp_commit();

        const __half* sA = sm + (kt % STAGES) * STAGE_H;
        const __half* sB = sA + A_STAGE;

#pragma unroll
        for (int ks = 0; ks < 2; ks++) {          // 2 k-steps of 16
            const int k0 = ks * 16;
            uint32_t af[4][4];
#pragma unroll
            for (int mi = 0; mi < 4; mi++)
                ldm4(af[mi], &sA[(wm + mi * 16 + a_row) * ASTRIDE + k0 + a_col]);
            uint32_t bf[8][2];
#pragma unroll
            for (int np = 0; np < 4; np++) {
                uint32_t r[4];
                ldm4(r, &sB[(wn + np * 16 + b_row) * BSTRIDE + k0 + b_col]);
                bf[2*np][0] = r[0]; bf[2*np][1] = r[1];
                bf[2*np+1][0] = r[2]; bf[2*np+1][1] = r[3];
            }
#pragma unroll
            for (int mi = 0; mi < 4; mi++)
#pragma unroll
                for (int ni = 0; ni < 8; ni++)
                    mma_f16(acc[mi][ni], af[mi], bf[ni]);
        }
    }
    __syncthreads();

    if (EPI != EPI_VT_H) {
#pragma unroll
        for (int mi = 0; mi < 4; mi++) {
#pragma unroll
            for (int ni = 0; ni < 8; ni++) {
                const int r = m0 + wm + mi * 16 + g;
                const int c = n0 + wn + ni * 8 + tg * 2;
#pragma unroll
                for (int h = 0; h < 2; h++) {
                    const int rr = r + h * 8;
                    float v0 = acc[mi][ni][h * 2 + 0];
                    float v1 = acc[mi][ni][h * 2 + 1];
                    if (EPI == EPI_BIAS_H || EPI == EPI_BIAS_RES_F || EPI == EPI_GELU_H) {
                        v0 += bias[c]; v1 += bias[c + 1];
                    }
                    if (EPI == EPI_BIAS_RES_F) {
                        v0 += res[(size_t)rr * N + c];
                        v1 += res[(size_t)rr * N + c + 1];
                    }
                    if (EPI == EPI_GELU_H) { v0 = gelu_exact(v0); v1 = gelu_exact(v1); }
                    const size_t o = (size_t)bz * cB + (size_t)rr * N + c;
                    if (EPI == EPI_STORE_F || EPI == EPI_BIAS_RES_F) {
                        *(float2*)&Cf[o] = make_float2(v0, v1);
                    } else {
                        *(__half2*)&Ch[o] = __floats2half2_rn(v0, v1);
                    }
                }
            }
        }
    } else {
        // stage fp16 C tile transposed in smem as [n][m], then write V^T coalesced
        __half* stg = sm;   // 128 x VT_STRIDE halves = 34816 B < SMEM_BYTES
#pragma unroll
        for (int mi = 0; mi < 4; mi++) {
#pragma unroll
            for (int ni = 0; ni < 8; ni++) {
                const int c = wn + ni * 8 + tg * 2;
                const float b0 = bias[n0 + c], b1 = bias[n0 + c + 1];
#pragma unroll
                for (int h = 0; h < 2; h++) {
                    const int r = wm + mi * 16 + g + h * 8;
                    stg[(c    ) * VT_STRIDE + r] = __float2half_rn(acc[mi][ni][h * 2 + 0] + b0);
                    stg[(c + 1) * VT_STRIDE + r] = __float2half_rn(acc[mi][ni][h * 2 + 1] + b1);
                }
            }
        }
        __syncthreads();
        const int b = m0 >> 11, t0 = m0 & 2047;
        for (int nr = warp * 32; nr < warp * 32 + 32; nr++) {
            const int n = n0 + nr;
            __half* dst = Ch + ((size_t)b * DIM + n) * SEQ + t0;
            const int m = lane * 4;
            *(uint2*)&dst[m] = *(uint2*)&stg[nr * VT_STRIDE + m];
        }
    }
}

// ---------------- weight transpose+convert: w[K][N] fp32 -> wt[N][K] fp16 ----------------
__global__ void wtrans_k(const float* __restrict__ w, __half* __restrict__ wt, int Kd, int Nd)
{
    __shared__ float t[32][33];
    const int bx = blockIdx.x, by = blockIdx.y;
    const int tx = threadIdx.x, ty = threadIdx.y;   // (32,8)
#pragma unroll
    for (int j = 0; j < 4; j++)
        t[ty + j * 8][tx] = w[(size_t)(by * 32 + ty + j * 8) * Nd + bx * 32 + tx];
    __syncthreads();
#pragma unroll
    for (int j = 0; j < 4; j++)
        wt[(size_t)(bx * 32 + ty + j * 8) * Kd + by * 32 + tx] = __float2half_rn(t[tx][ty + j * 8]);
}

// ---------------- RMSNorm: fp32 in -> fp16 out ----------------
__global__ void __launch_bounds__(256, 1)
rmsnorm_k(const float* __restrict__ x, const float* __restrict__ w, __half* __restrict__ o)
{
    __shared__ float red[8];
    __shared__ float bc;
    const int row = blockIdx.x;
    const size_t base = (size_t)row * DIM;
    const int tid = threadIdx.x, lane = tid & 31, warp = tid >> 5;

    float4 xv = ((const float4*)(x + base))[tid];
    float ss = xv.x * xv.x + xv.y * xv.y + xv.z * xv.z + xv.w * xv.w;
#pragma unroll
    for (int off = 16; off; off >>= 1) ss += __shfl_xor_sync(0xffffffffu, ss, off);
    if (lane == 0) red[warp] = ss;
    __syncthreads();
    if (tid == 0) {
        float t = 0.0f;
#pragma unroll
        for (int i = 0; i < 8; i++) t += red[i];
        bc = rsqrtf(t * (1.0f / DIM) + 1e-6f);
    }
    __syncthreads();
    const float inv = bc;
    float4 wv = ((const float4*)w)[tid];
    __half2 h0 = __floats2half2_rn(xv.x * inv * wv.x, xv.y * inv * wv.y);
    __half2 h1 = __floats2half2_rn(xv.z * inv * wv.z, xv.w * inv * wv.w);
    *(__half2*)&o[base + tid * 4 + 0] = h0;
    *(__half2*)&o[base + tid * 4 + 2] = h1;
}

// ---------------- causal softmax: fp32 scores -> fp16 P, zero-fill to 128-edge ----------------
__global__ void __launch_bounds__(256, 1)
softmax_k(const float* __restrict__ s, __half* __restrict__ p)
{
    __shared__ float red[8];
    __shared__ float bc;
    const int t = blockIdx.x, b = blockIdx.y;
    const size_t rbase = ((size_t)b * SEQ + (size_t)t) * SEQ;
    const float* row = s + rbase;
    const int L = t + 1;
    const int tid = threadIdx.x, lane = tid & 31, warp = tid >> 5;
    const float scale = 0.03125f;  // 1/sqrt(1024)

    float m = -3.4e38f;
    for (int j = tid; j < L; j += 256) m = fmaxf(m, row[j]);
#pragma unroll
    for (int off = 16; off; off >>= 1) m = fmaxf(m, __shfl_xor_sync(0xffffffffu, m, off));
    if (lane == 0) red[warp] = m;
    __syncthreads();
    if (tid == 0) {
        float mm = red[0];
#pragma unroll
        for (int i = 1; i < 8; i++) mm = fmaxf(mm, red[i]);
        bc = mm;
    }
    __syncthreads();
    const float mm = bc;
    __syncthreads();

    float sum = 0.0f;
    for (int j = tid; j < L; j += 256) sum += expf((row[j] - mm) * scale);
#pragma unroll
    for (int off = 16; off; off >>= 1) sum += __shfl_xor_sync(0xffffffffu, sum, off);
    if (lane == 0) red[warp] = sum;
    __syncthreads();
    if (tid == 0) {
        float ss = 0.0f;
#pragma unroll
        for (int i = 0; i < 8; i++) ss += red[i];
        bc = 1.0f / ss;
    }
    __syncthreads();
    const float inv = bc;
    for (int j = tid; j < L; j += 256)
        p[rbase + j] = __float2half_rn(expf((row[j] - mm) * scale) * inv);

    const int jend = ((t >> 7) + 1) << 7;
    const __half z = __float2half_rn(0.0f);
    for (int j = L + tid; j < jend; j += 256) p[rbase + j] = z;
}

// ---------------- launch ----------------
extern "C" void kernel_launch(void* const* d_in, const int* in_sizes, int n_in,
                              void* d_out, int out_size)
{
    (void)in_sizes; (void)n_in; (void)out_size;
    const float* x   = (const float*)d_in[0];
    const float* anw = (const float*)d_in[1];
    const float* mnw = (const float*)d_in[2];
    const float* wq  = (const float*)d_in[3];
    const float* bq  = (const float*)d_in[4];
    const float* wk  = (const float*)d_in[5];
    const float* bk  = (const float*)d_in[6];
    const float* wv  = (const float*)d_in[7];
    const float* bv  = (const float*)d_in[8];
    const float* wo  = (const float*)d_in[9];
    const float* bo  = (const float*)d_in[10];
    const float* w1  = (const float*)d_in[11];
    const float* b1  = (const float*)d_in[12];
    const float* w2  = (const float*)d_in[13];
    const float* b2  = (const float*)d_in[14];
    float* out = (float*)d_out;

    __half *xn, *q, *k, *vt, *attn, *h1, *p;
    __half *wqt, *wkt, *wvt, *wot, *w1t, *w2t;
    float *sc, *xmid;
    cudaGetSymbolAddress((void**)&xn,   g_xn);
    cudaGetSymbolAddress((void**)&q,    g_q);
    cudaGetSymbolAddress((void**)&k,    g_k);
    cudaGetSymbolAddress((void**)&vt,   g_vt);
    cudaGetSymbolAddress((void**)&attn, g_attn);
    cudaGetSymbolAddress((void**)&h1,   g_h1);
    cudaGetSymbolAddress((void**)&p,    g_p);
    cudaGetSymbolAddress((void**)&sc,   g_sc);
    cudaGetSymbolAddress((void**)&xmid, g_xmid);
    cudaGetSymbolAddress((void**)&wqt,  g_wqt);
    cudaGetSymbolAddress((void**)&wkt,  g_wkt);
    cudaGetSymbolAddress((void**)&wvt,  g_wvt);
    cudaGetSymbolAddress((void**)&wot,  g_wot);
    cudaGetSymbolAddress((void**)&w1t,  g_w1t);
    cudaGetSymbolAddress((void**)&w2t,  g_w2t);

    cudaFuncSetAttribute(gemm_k<EPI_BIAS_H,     false, false>,
                         cudaFuncAttributeMaxDynamicSharedMemorySize, SMEM_BYTES);
    cudaFuncSetAttribute(gemm_k<EPI_VT_H,       false, false>,
                         cudaFuncAttributeMaxDynamicSharedMemorySize, SMEM_BYTES);
    cudaFuncSetAttribute(gemm_k<EPI_STORE_F,    true,  false>,
                         cudaFuncAttributeMaxDynamicSharedMemorySize, SMEM_BYTES);
    cudaFuncSetAttribute(gemm_k<EPI_STORE_H,    false, true >,
                         cudaFuncAttributeMaxDynamicSharedMemorySize, SMEM_BYTES);
    cudaFuncSetAttribute(gemm_k<EPI_BIAS_RES_F, false, false>,
                         cudaFuncAttributeMaxDynamicSharedMemorySize, SMEM_BYTES);
    cudaFuncSetAttribute(gemm_k<EPI_GELU_H,     false, false>,
                         cudaFuncAttributeMaxDynamicSharedMemorySize, SMEM_BYTES);

    const long long SD = (long long)SEQ * DIM;
    const long long SS = (long long)SEQ * SEQ;
    const dim3 wb(32, 8);

    // 0) transpose+convert weights to fp16 [N][K]
    wtrans_k<<<dim3(DIM/32, DIM/32), wb>>>(wq, wqt, DIM, DIM);
    wtrans_k<<<dim3(DIM/32, DIM/32), wb>>>(wk, wkt, DIM, DIM);
    wtrans_k<<<dim3(DIM/32, DIM/32), wb>>>(wv, wvt, DIM, DIM);
    wtrans_k<<<dim3(DIM/32, DIM/32), wb>>>(wo, wot, DIM, DIM);
    wtrans_k<<<dim3(HID/32, DIM/32), wb>>>(w1, w1t, DIM, HID);
    wtrans_k<<<dim3(DIM/32, HID/32), wb>>>(w2, w2t, HID, DIM);

    // 1) xn = rmsnorm(x) * attn_norm_w  (fp16)
    rmsnorm_k<<<ROWS, 256>>>(x, anw, xn);

    // 2) Q, K fp16; V written transposed as V^T fp16
    gemm_k<EPI_BIAS_H, false, false><<<dim3(DIM/NT, ROWS/MT, 1), CTHREADS, SMEM_BYTES>>>(
        xn, wqt, bq, nullptr, nullptr, q, ROWS, DIM, DIM, 0, 0, 0);
    gemm_k<EPI_BIAS_H, false, false><<<dim3(DIM/NT, ROWS/MT, 1), CTHREADS, SMEM_BYTES>>>(
        xn, wkt, bk, nullptr, nullptr, k, ROWS, DIM, DIM, 0, 0, 0);
    gemm_k<EPI_VT_H, false, false><<<dim3(DIM/NT, ROWS/MT, 1), CTHREADS, SMEM_BYTES>>>(
        xn, wvt, bv, nullptr, nullptr, vt, ROWS, DIM, DIM, 0, 0, 0);

    // 3) scores = Q @ K^T (fp32 out, causal block-skip)
    gemm_k<EPI_STORE_F, true, false><<<dim3(SEQ/NT, SEQ/MT, BATCH), CTHREADS, SMEM_BYTES>>>(
        q, k, nullptr, nullptr, sc, nullptr, SEQ, SEQ, DIM, SD, SD, SS);

    // 4) causal softmax -> P fp16
    softmax_k<<<dim3(SEQ, BATCH), 256>>>(sc, p);

    // 5) attn = P @ V  (B = V^T [d][s], K loop truncated, fp16 out)
    gemm_k<EPI_STORE_H, false, true><<<dim3(DIM/NT, SEQ/MT, BATCH), CTHREADS, SMEM_BYTES>>>(
        p, vt, nullptr, nullptr, nullptr, attn, SEQ, DIM, SEQ, SS, SD, SD);

    // 6) xmid = x + attn @ wo + bo  (fp32)
    gemm_k<EPI_BIAS_RES_F, false, false><<<dim3(DIM/NT, ROWS/MT, 1), CTHREADS, SMEM_BYTES>>>(
        attn, wot, bo, x, xmid, nullptr, ROWS, DIM, DIM, 0, 0, 0);

    // 7) h = rmsnorm(xmid) * mlp_norm_w  (fp16)
    rmsnorm_k<<<ROWS, 256>>>(xmid, mnw, xn);

    // 8) h1 = gelu(h @ w1 + b1)  (fp16)
    gemm_k<EPI_GELU_H, false, false><<<dim3(HID/NT, ROWS/MT, 1), CTHREADS, SMEM_BYTES>>>(
        xn, w1t, b1, nullptr, nullptr, h1, ROWS, HID, DIM, 0, 0, 0);

    // 9) out = xmid + h1 @ w2 + b2  (fp32)
    gemm_k<EPI_BIAS_RES_F, false, false><<<dim3(DIM/NT, ROWS/MT, 1), CTHREADS, SMEM_BYTES>>>(
        h1, w2t, b2, xmid, out, nullptr, ROWS, DIM, HID, 0, 0, 0);
}

// round 8
// speedup vs baseline: 2.4700x; 1.0354x over previous
#include <cuda_runtime.h>
#include <cuda_fp16.h>
#include <cstdint>
#include <math.h>

#define BATCH 8
#define SEQ   2048
#define DIM   1024
#define HID   4096
#define ROWS  (BATCH*SEQ)   /* 16384 */

// GEMM tiling: CTA 128x128x32, 4 warps of 64x64, fp16 operands, 2 CTAs/SM
#define MT 128
#define NT 128
#define KT 32
#define CTHREADS 128
#define STAGES 4
#define ASTRIDE 40                       /* halves per A-row (32 + 8 pad) */
#define BSTRIDE 40
#define A_STAGE (MT*ASTRIDE)             /* 5120 halves */
#define B_STAGE (NT*BSTRIDE)             /* 5120 halves */
#define STAGE_H (A_STAGE + B_STAGE)      /* 10240 halves = 20480 B */
#define SMEM_BYTES (STAGES*STAGE_H*2)    /* 81920 B -> 2 CTAs/SM */
#define VT_STRIDE 136                    /* halves, V^T staging */

// exp constants: E = 2^(s*K1 - K2) = e^(s/32 - 4)
#define K1EXP 0.04508422f                /* log2(e)/32 */
#define K2EXP 5.77078016f                /* 4*log2(e)  */
#define NTILES_S (SEQ/NT)                /* 16 */

// ---------------- scratch (allocation-free: __device__ globals) ----------------
static __device__ __half g_xn  [(size_t)ROWS*DIM];
static __device__ __half g_q   [(size_t)ROWS*DIM];
static __device__ __half g_k   [(size_t)ROWS*DIM];
static __device__ __half g_vt  [(size_t)ROWS*DIM];     // V^T: [b][d][s]
static __device__ __half g_attn[(size_t)ROWS*DIM];
static __device__ __half g_h1  [(size_t)ROWS*HID];
static __device__ __half g_e   [(size_t)BATCH*SEQ*SEQ]; // unnormalized exp(scores)
static __device__ float  g_psum[(size_t)BATCH*NTILES_S*SEQ]; // per-tile row partial sums
static __device__ float  g_xmid[(size_t)ROWS*DIM];
// weights transposed to [N][K], fp16
static __device__ __half g_wqt [(size_t)DIM*DIM];
static __device__ __half g_wkt [(size_t)DIM*DIM];
static __device__ __half g_wvt [(size_t)DIM*DIM];
static __device__ __half g_wot [(size_t)DIM*DIM];
static __device__ __half g_w1t [(size_t)HID*DIM];
static __device__ __half g_w2t [(size_t)DIM*HID];

// ---------------- helpers ----------------
__device__ __forceinline__ float gelu_exact(float x) {
    return 0.5f * x * (1.0f + erff(x * 0.70710678118654752440f));
}
__device__ __forceinline__ float ex2a(float x) {
    float r;
    asm("ex2.approx.ftz.f32 %0, %1;" : "=f"(r) : "f"(x));
    return r;
}

__device__ __forceinline__ void mma_f16(float d[4], const uint32_t a[4], const uint32_t b[2]) {
    asm volatile(
        "mma.sync.aligned.m16n8k16.row.col.f32.f16.f16.f32 "
        "{%0,%1,%2,%3}, {%4,%5,%6,%7}, {%8,%9}, {%0,%1,%2,%3};\n"
        : "+f"(d[0]), "+f"(d[1]), "+f"(d[2]), "+f"(d[3])
        : "r"(a[0]), "r"(a[1]), "r"(a[2]), "r"(a[3]), "r"(b[0]), "r"(b[1]));
}

__device__ __forceinline__ void ldm4(uint32_t r[4], const __half* p) {
    uint32_t a = (uint32_t)__cvta_generic_to_shared(p);
    asm volatile("ldmatrix.sync.aligned.m8n8.x4.shared.b16 {%0,%1,%2,%3}, [%4];\n"
                 : "=r"(r[0]), "=r"(r[1]), "=r"(r[2]), "=r"(r[3]) : "r"(a));
}

__device__ __forceinline__ void cp16(__half* smem, const __half* gmem) {
    uint32_t s = (uint32_t)__cvta_generic_to_shared(smem);
    asm volatile("cp.async.cg.shared.global [%0], [%1], 16;\n" :: "r"(s), "l"(gmem));
}
__device__ __forceinline__ void cp_commit() { asm volatile("cp.async.commit_group;\n"); }
template<int N>
__device__ __forceinline__ void cp_wait() { asm volatile("cp.async.wait_group %0;\n" :: "n"(N)); }

// ---------------- GEMM ----------------
// C[M,N] = A[M,K] @ B^T + epi; A fp16 [M][K], B fp16 [N][K] k-major.
//   CAUSAL : skip CTA if N-tile fully above diagonal (square 128 tiles)
//   PVT    : truncate K loop at end of this M-tile (P@V causal structure)
#define EPI_STORE_F    0   /* fp32 store */
#define EPI_BIAS_H     1   /* q,k: bias, fp16 store */
#define EPI_BIAS_RES_F 2   /* xmid/out: bias+residual, fp32 store */
#define EPI_GELU_H     3   /* h1: gelu(bias), fp16 store */
#define EPI_VT_H       4   /* v: bias, fp16 store transposed as V^T */
#define EPI_STORE_H    5   /* fp16 store */
#define EPI_EXP_H      6   /* scores: exp + row partial sums (Cf=psum), fp16 E store */
#define EPI_DIV_H      7   /* attn: divide by rowsum (res=psum), fp16 store */

template<int EPI, bool CAUSAL, bool PVT>
__global__ void __launch_bounds__(CTHREADS, 2)
gemm_k(const __half* __restrict__ A, const __half* __restrict__ B,
       const float* __restrict__ bias, const float* __restrict__ res,
       float* __restrict__ Cf, __half* __restrict__ Ch,
       int M, int N, int K,
       long long aB, long long bB, long long cB)
{
    const int bn = blockIdx.x, bm = blockIdx.y, bz = blockIdx.z;
    if (CAUSAL && bn > bm) return;
    A += (long long)bz * aB;
    B += (long long)bz * bB;

    extern __shared__ __half sm[];

    const int tid  = threadIdx.x;
    const int lane = tid & 31;
    const int warp = tid >> 5;
    const int wm = (warp >> 1) * 64;   // 2 warps along M (64 rows each)
    const int wn = (warp & 1) * 64;    // 2 warps along N (64 cols each)
    const int g  = lane >> 2;
    const int tg = lane & 3;
    const int m0 = bm * MT, n0 = bn * NT;

    int ktiles = K / KT;
    if (PVT) { int kt2 = (bm + 1) * (MT / KT); if (kt2 < ktiles) ktiles = kt2; }

    float acc[4][8][4];
#pragma unroll
    for (int i = 0; i < 4; i++)
#pragma unroll
        for (int j = 0; j < 8; j++)
#pragma unroll
            for (int r = 0; r < 4; r++) acc[i][j][r] = 0.0f;

    // ldmatrix per-lane selectors (halves)
    const int l8 = lane & 7, q = lane >> 3;
    const int a_row = (q & 1) * 8 + l8;
    const int a_col = (q >> 1) * 8;
    const int b_row = (q >> 1) * 8 + l8;
    const int b_col = (q & 1) * 8;

    auto issue = [&](int stage, int kt) {
        __half* sA = sm + stage * STAGE_H;
        __half* sB = sA + A_STAGE;
#pragma unroll
        for (int i = 0; i < 4; i++) {             // A: 128 rows x 4 chunks of 16B
            const int idx = tid + i * CTHREADS;
            const int row = idx >> 2, ch = idx & 3;
            cp16(&sA[row * ASTRIDE + ch * 8],
                 A + (size_t)(m0 + row) * K + kt * KT + ch * 8);
        }
#pragma unroll
        for (int i = 0; i < 4; i++) {             // B: 128 n-rows x 4 chunks
            const int idx = tid + i * CTHREADS;
            const int row = idx >> 2, ch = idx & 3;
            cp16(&sB[row * BSTRIDE + ch * 8],
                 B + (size_t)(n0 + row) * K + kt * KT + ch * 8);
        }
    };

#pragma unroll
    for (int s = 0; s < STAGES - 1; s++) {
        if (s < ktiles) issue(s, s);
        cp_commit();
    }

    for (int kt = 0; kt < ktiles; kt++) {
        cp_wait<STAGES - 2>();
        __syncthreads();

        const int nkt = kt + STAGES - 1;
        if (nkt < ktiles) issue(nkt % STAGES, nkt);
        cp_commit();

        const __half* sA = sm + (kt % STAGES) * STAGE_H;
        const __half* sB = sA + A_STAGE;

#pragma unroll
        for (int ks = 0; ks < 2; ks++) {
            const int k0 = ks * 16;
            uint32_t af[4][4];
#pragma unroll
            for (int mi = 0; mi < 4; mi++)
                ldm4(af[mi], &sA[(wm + mi * 16 + a_row) * ASTRIDE + k0 + a_col]);
            uint32_t bf[8][2];
#pragma unroll
            for (int np = 0; np < 4; np++) {
                uint32_t r[4];
                ldm4(r, &sB[(wn + np * 16 + b_row) * BSTRIDE + k0 + b_col]);
                bf[2*np][0] = r[0]; bf[2*np][1] = r[1];
                bf[2*np+1][0] = r[2]; bf[2*np+1][1] = r[3];
            }
#pragma unroll
            for (int mi = 0; mi < 4; mi++)
#pragma unroll
                for (int ni = 0; ni < 8; ni++)
                    mma_f16(acc[mi][ni], af[mi], bf[ni]);
        }
    }
    __syncthreads();

    // ---- special epilogue preambles ----
    if (EPI == EPI_EXP_H) {
        // exp-transform acc in place, compute per-row partial sums -> psum (Cf)
        const bool diag = (bn == bm);
        float* ps = (float*)sm;   // [128 rows][2 warp-halves]
#pragma unroll
        for (int mi = 0; mi < 4; mi++) {
#pragma unroll
            for (int h = 0; h < 2; h++) {
                const int rl = wm + mi * 16 + g + h * 8;
                const int rr = m0 + rl;
                float s8 = 0.0f;
#pragma unroll
                for (int ni = 0; ni < 8; ni++) {
#pragma unroll
                    for (int e2 = 0; e2 < 2; e2++) {
                        const int c = n0 + wn + ni * 8 + tg * 2 + e2;
                        float v = acc[mi][ni][h * 2 + e2];
                        float ev = (diag && c > rr) ? 0.0f
                                 : ex2a(fmaf(v, K1EXP, -K2EXP));
                        acc[mi][ni][h * 2 + e2] = ev;
                        s8 += ev;
                    }
                }
                s8 += __shfl_xor_sync(0xffffffffu, s8, 1);
                s8 += __shfl_xor_sync(0xffffffffu, s8, 2);
                if (tg == 0) ps[rl * 2 + (warp & 1)] = s8;
            }
        }
        __syncthreads();
        if (tid < MT)
            Cf[((size_t)bz * NTILES_S + bn) * SEQ + m0 + tid] = ps[tid * 2] + ps[tid * 2 + 1];
    }

    float* rs = (float*)sm;       // rowscale for EPI_DIV_H
    if (EPI == EPI_DIV_H) {
        if (tid < MT) {
            const float* pp = res + (size_t)bz * NTILES_S * SEQ + m0 + tid;
            float s = 0.0f;
            for (int j = 0; j <= bm; j++) s += pp[(size_t)j * SEQ];
            rs[tid] = 1.0f / s;
        }
        __syncthreads();
    }

    // ---- stores ----
    if (EPI != EPI_VT_H) {
#pragma unroll
        for (int mi = 0; mi < 4; mi++) {
#pragma unroll
            for (int ni = 0; ni < 8; ni++) {
                const int rl = wm + mi * 16 + g;
                const int c = n0 + wn + ni * 8 + tg * 2;
#pragma unroll
                for (int h = 0; h < 2; h++) {
                    const int rr = m0 + rl + h * 8;
                    float v0 = acc[mi][ni][h * 2 + 0];
                    float v1 = acc[mi][ni][h * 2 + 1];
                    if (EPI == EPI_BIAS_H || EPI == EPI_BIAS_RES_F || EPI == EPI_GELU_H) {
                        v0 += bias[c]; v1 += bias[c + 1];
                    }
                    if (EPI == EPI_BIAS_RES_F) {
                        v0 += res[(size_t)rr * N + c];
                        v1 += res[(size_t)rr * N + c + 1];
                    }
                    if (EPI == EPI_GELU_H) { v0 = gelu_exact(v0); v1 = gelu_exact(v1); }
                    if (EPI == EPI_DIV_H) {
                        const float sc_ = rs[rl + h * 8];
                        v0 *= sc_; v1 *= sc_;
                    }
                    const size_t o = (size_t)bz * cB + (size_t)rr * N + c;
                    if (EPI == EPI_STORE_F || EPI == EPI_BIAS_RES_F) {
                        *(float2*)&Cf[o] = make_float2(v0, v1);
                    } else {
                        *(__half2*)&Ch[o] = __floats2half2_rn(v0, v1);
                    }
                }
            }
        }
    } else {
        // stage fp16 C tile transposed in smem as [n][m], then write V^T coalesced
        __half* stg = sm;
#pragma unroll
        for (int mi = 0; mi < 4; mi++) {
#pragma unroll
            for (int ni = 0; ni < 8; ni++) {
                const int c = wn + ni * 8 + tg * 2;
                const float b0 = bias[n0 + c], b1 = bias[n0 + c + 1];
#pragma unroll
                for (int h = 0; h < 2; h++) {
                    const int r = wm + mi * 16 + g + h * 8;
                    stg[(c    ) * VT_STRIDE + r] = __float2half_rn(acc[mi][ni][h * 2 + 0] + b0);
                    stg[(c + 1) * VT_STRIDE + r] = __float2half_rn(acc[mi][ni][h * 2 + 1] + b1);
                }
            }
        }
        __syncthreads();
        const int b = m0 >> 11, t0 = m0 & 2047;
        for (int nr = warp * 32; nr < warp * 32 + 32; nr++) {
            const int n = n0 + nr;
            __half* dst = Ch + ((size_t)b * DIM + n) * SEQ + t0;
            const int m = lane * 4;
            *(uint2*)&dst[m] = *(uint2*)&stg[nr * VT_STRIDE + m];
        }
    }
}

// ---------------- weight transpose+convert: w[K][N] fp32 -> wt[N][K] fp16 ----------------
__global__ void wtrans_k(const float* __restrict__ w, __half* __restrict__ wt, int Kd, int Nd)
{
    __shared__ float t[32][33];
    const int bx = blockIdx.x, by = blockIdx.y;
    const int tx = threadIdx.x, ty = threadIdx.y;   // (32,8)
#pragma unroll
    for (int j = 0; j < 4; j++)
        t[ty + j * 8][tx] = w[(size_t)(by * 32 + ty + j * 8) * Nd + bx * 32 + tx];
    __syncthreads();
#pragma unroll
    for (int j = 0; j < 4; j++)
        wt[(size_t)(bx * 32 + ty + j * 8) * Kd + by * 32 + tx] = __float2half_rn(t[tx][ty + j * 8]);
}

// ---------------- RMSNorm: fp32 in -> fp16 out ----------------
__global__ void __launch_bounds__(256, 1)
rmsnorm_k(const float* __restrict__ x, const float* __restrict__ w, __half* __restrict__ o)
{
    __shared__ float red[8];
    __shared__ float bc;
    const int row = blockIdx.x;
    const size_t base = (size_t)row * DIM;
    const int tid = threadIdx.x, lane = tid & 31, warp = tid >> 5;

    float4 xv = ((const float4*)(x + base))[tid];
    float ss = xv.x * xv.x + xv.y * xv.y + xv.z * xv.z + xv.w * xv.w;
#pragma unroll
    for (int off = 16; off; off >>= 1) ss += __shfl_xor_sync(0xffffffffu, ss, off);
    if (lane == 0) red[warp] = ss;
    __syncthreads();
    if (tid == 0) {
        float t = 0.0f;
#pragma unroll
        for (int i = 0; i < 8; i++) t += red[i];
        bc = rsqrtf(t * (1.0f / DIM) + 1e-6f);
    }
    __syncthreads();
    const float inv = bc;
    float4 wv = ((const float4*)w)[tid];
    __half2 h0 = __floats2half2_rn(xv.x * inv * wv.x, xv.y * inv * wv.y);
    __half2 h1 = __floats2half2_rn(xv.z * inv * wv.z, xv.w * inv * wv.w);
    *(__half2*)&o[base + tid * 4 + 0] = h0;
    *(__half2*)&o[base + tid * 4 + 2] = h1;
}

// ---------------- launch ----------------
extern "C" void kernel_launch(void* const* d_in, const int* in_sizes, int n_in,
                              void* d_out, int out_size)
{
    (void)in_sizes; (void)n_in; (void)out_size;
    const float* x   = (const float*)d_in[0];
    const float* anw = (const float*)d_in[1];
    const float* mnw = (const float*)d_in[2];
    const float* wq  = (const float*)d_in[3];
    const float* bq  = (const float*)d_in[4];
    const float* wk  = (const float*)d_in[5];
    const float* bk  = (const float*)d_in[6];
    const float* wv  = (const float*)d_in[7];
    const float* bv  = (const float*)d_in[8];
    const float* wo  = (const float*)d_in[9];
    const float* bo  = (const float*)d_in[10];
    const float* w1  = (const float*)d_in[11];
    const float* b1  = (const float*)d_in[12];
    const float* w2  = (const float*)d_in[13];
    const float* b2  = (const float*)d_in[14];
    float* out = (float*)d_out;

    __half *xn, *q, *k, *vt, *attn, *h1, *e;
    __half *wqt, *wkt, *wvt, *wot, *w1t, *w2t;
    float *psum, *xmid;
    cudaGetSymbolAddress((void**)&xn,   g_xn);
    cudaGetSymbolAddress((void**)&q,    g_q);
    cudaGetSymbolAddress((void**)&k,    g_k);
    cudaGetSymbolAddress((void**)&vt,   g_vt);
    cudaGetSymbolAddress((void**)&attn, g_attn);
    cudaGetSymbolAddress((void**)&h1,   g_h1);
    cudaGetSymbolAddress((void**)&e,    g_e);
    cudaGetSymbolAddress((void**)&psum, g_psum);
    cudaGetSymbolAddress((void**)&xmid, g_xmid);
    cudaGetSymbolAddress((void**)&wqt,  g_wqt);
    cudaGetSymbolAddress((void**)&wkt,  g_wkt);
    cudaGetSymbolAddress((void**)&wvt,  g_wvt);
    cudaGetSymbolAddress((void**)&wot,  g_wot);
    cudaGetSymbolAddress((void**)&w1t,  g_w1t);
    cudaGetSymbolAddress((void**)&w2t,  g_w2t);

    cudaFuncSetAttribute(gemm_k<EPI_BIAS_H,     false, false>,
                         cudaFuncAttributeMaxDynamicSharedMemorySize, SMEM_BYTES);
    cudaFuncSetAttribute(gemm_k<EPI_VT_H,       false, false>,
                         cudaFuncAttributeMaxDynamicSharedMemorySize, SMEM_BYTES);
    cudaFuncSetAttribute(gemm_k<EPI_EXP_H,      true,  false>,
                         cudaFuncAttributeMaxDynamicSharedMemorySize, SMEM_BYTES);
    cudaFuncSetAttribute(gemm_k<EPI_DIV_H,      false, true >,
                         cudaFuncAttributeMaxDynamicSharedMemorySize, SMEM_BYTES);
    cudaFuncSetAttribute(gemm_k<EPI_BIAS_RES_F, false, false>,
                         cudaFuncAttributeMaxDynamicSharedMemorySize, SMEM_BYTES);
    cudaFuncSetAttribute(gemm_k<EPI_GELU_H,     false, false>,
                         cudaFuncAttributeMaxDynamicSharedMemorySize, SMEM_BYTES);

    const long long SD = (long long)SEQ * DIM;
    const long long SS = (long long)SEQ * SEQ;
    const dim3 wb(32, 8);

    // 0) transpose+convert weights to fp16 [N][K]
    wtrans_k<<<dim3(DIM/32, DIM/32), wb>>>(wq, wqt, DIM, DIM);
    wtrans_k<<<dim3(DIM/32, DIM/32), wb>>>(wk, wkt, DIM, DIM);
    wtrans_k<<<dim3(DIM/32, DIM/32), wb>>>(wv, wvt, DIM, DIM);
    wtrans_k<<<dim3(DIM/32, DIM/32), wb>>>(wo, wot, DIM, DIM);
    wtrans_k<<<dim3(HID/32, DIM/32), wb>>>(w1, w1t, DIM, HID);
    wtrans_k<<<dim3(DIM/32, HID/32), wb>>>(w2, w2t, HID, DIM);

    // 1) xn = rmsnorm(x) * attn_norm_w  (fp16)
    rmsnorm_k<<<ROWS, 256>>>(x, anw, xn);

    // 2) Q, K fp16; V written transposed as V^T fp16
    gemm_k<EPI_BIAS_H, false, false><<<dim3(DIM/NT, ROWS/MT, 1), CTHREADS, SMEM_BYTES>>>(
        xn, wqt, bq, nullptr, nullptr, q, ROWS, DIM, DIM, 0, 0, 0);
    gemm_k<EPI_BIAS_H, false, false><<<dim3(DIM/NT, ROWS/MT, 1), CTHREADS, SMEM_BYTES>>>(
        xn, wkt, bk, nullptr, nullptr, k, ROWS, DIM, DIM, 0, 0, 0);
    gemm_k<EPI_VT_H, false, false><<<dim3(DIM/NT, ROWS/MT, 1), CTHREADS, SMEM_BYTES>>>(
        xn, wvt, bv, nullptr, nullptr, vt, ROWS, DIM, DIM, 0, 0, 0);

    // 3) E = exp(QK^T/32 - 4) fp16 + per-tile row sums (causal block-skip, in-tile mask)
    gemm_k<EPI_EXP_H, true, false><<<dim3(SEQ/NT, SEQ/MT, BATCH), CTHREADS, SMEM_BYTES>>>(
        q, k, nullptr, nullptr, psum, e, SEQ, SEQ, DIM, SD, SD, SS);

    // 4) attn = (E @ V) / rowsum  (B = V^T [d][s], K loop truncated)
    gemm_k<EPI_DIV_H, false, true><<<dim3(DIM/NT, SEQ/MT, BATCH), CTHREADS, SMEM_BYTES>>>(
        e, vt, nullptr, psum, nullptr, attn, SEQ, DIM, SEQ, SS, SD, SD);

    // 5) xmid = x + attn @ wo + bo  (fp32)
    gemm_k<EPI_BIAS_RES_F, false, false><<<dim3(DIM/NT, ROWS/MT, 1), CTHREADS, SMEM_BYTES>>>(
        attn, wot, bo, x, xmid, nullptr, ROWS, DIM, DIM, 0, 0, 0);

    // 6) h = rmsnorm(xmid) * mlp_norm_w  (fp16)
    rmsnorm_k<<<ROWS, 256>>>(xmid, mnw, xn);

    // 7) h1 = gelu(h @ w1 + b1)  (fp16)
    gemm_k<EPI_GELU_H, false, false><<<dim3(HID/NT, ROWS/MT, 1), CTHREADS, SMEM_BYTES>>>(
        xn, w1t, b1, nullptr, nullptr, h1, ROWS, HID, DIM, 0, 0, 0);

    // 8) out = xmid + h1 @ w2 + b2  (fp32)
    gemm_k<EPI_BIAS_RES_F, false, false><<<dim3(DIM/NT, ROWS/MT, 1), CTHREADS, SMEM_BYTES>>>(
        h1, w2t, b2, xmid, out, nullptr, ROWS, DIM, HID, 0, 0, 0);
}

// round 10
// speedup vs baseline: 2.6547x; 1.0748x over previous
#include <cuda_runtime.h>
#include <cuda_fp16.h>
#include <cstdint>
#include <math.h>

#define BATCH 8
#define SEQ   2048
#define DIM   1024
#define HID   4096
#define ROWS  (BATCH*SEQ)   /* 16384 */

// GEMM tiling: CTA 128x128x64, 4 warps of 64x64, fp16 operands, 2 CTAs/SM
#define MT 128
#define NT 128
#define KT 64
#define CTHREADS 128
#define STAGES 3
#define ASTRIDE 72                       /* halves per A-row (64 + 8 pad) */
#define BSTRIDE 72
#define A_STAGE (MT*ASTRIDE)             /* 9216 halves */
#define B_STAGE (NT*BSTRIDE)             /* 9216 halves */
#define STAGE_H (A_STAGE + B_STAGE)      /* 18432 halves = 36864 B */
#define SMEM_BYTES (STAGES*STAGE_H*2)    /* 110592 B -> 2 CTAs/SM */
#define VT_STRIDE 136                    /* halves, V^T staging */

// exp constants: E = 2^(s*K1 - K2) = e^(s/32 - 4)
#define K1EXP 0.04508422f                /* log2(e)/32 */
#define K2EXP 5.77078016f                /* 4*log2(e)  */
#define NTILES_S (SEQ/NT)                /* 16 */

// ---------------- scratch (allocation-free: __device__ globals) ----------------
static __device__ __half g_xn  [(size_t)ROWS*DIM];
static __device__ __half g_q   [(size_t)ROWS*DIM];
static __device__ __half g_k   [(size_t)ROWS*DIM];
static __device__ __half g_vt  [(size_t)ROWS*DIM];     // V^T: [b][d][s]
static __device__ __half g_attn[(size_t)ROWS*DIM];
static __device__ __half g_h1  [(size_t)ROWS*HID];
static __device__ __half g_e   [(size_t)BATCH*SEQ*SEQ]; // unnormalized exp(scores)
static __device__ float  g_psum[(size_t)BATCH*NTILES_S*SEQ]; // per-tile row partial sums
static __device__ float  g_xmid[(size_t)ROWS*DIM];
// weights transposed to [N][K], fp16
static __device__ __half g_wqt [(size_t)DIM*DIM];
static __device__ __half g_wkt [(size_t)DIM*DIM];
static __device__ __half g_wvt [(size_t)DIM*DIM];
static __device__ __half g_wot [(size_t)DIM*DIM];
static __device__ __half g_w1t [(size_t)HID*DIM];
static __device__ __half g_w2t [(size_t)DIM*HID];

// ---------------- helpers ----------------
__device__ __forceinline__ float gelu_exact(float x) {
    return 0.5f * x * (1.0f + erff(x * 0.70710678118654752440f));
}
__device__ __forceinline__ float ex2a(float x) {
    float r;
    asm("ex2.approx.ftz.f32 %0, %1;" : "=f"(r) : "f"(x));
    return r;
}

__device__ __forceinline__ void mma_f16(float d[4], const uint32_t a[4], const uint32_t b[2]) {
    asm volatile(
        "mma.sync.aligned.m16n8k16.row.col.f32.f16.f16.f32 "
        "{%0,%1,%2,%3}, {%4,%5,%6,%7}, {%8,%9}, {%0,%1,%2,%3};\n"
        : "+f"(d[0]), "+f"(d[1]), "+f"(d[2]), "+f"(d[3])
        : "r"(a[0]), "r"(a[1]), "r"(a[2]), "r"(a[3]), "r"(b[0]), "r"(b[1]));
}

__device__ __forceinline__ void ldm4(uint32_t r[4], const __half* p) {
    uint32_t a = (uint32_t)__cvta_generic_to_shared(p);
    asm volatile("ldmatrix.sync.aligned.m8n8.x4.shared.b16 {%0,%1,%2,%3}, [%4];\n"
                 : "=r"(r[0]), "=r"(r[1]), "=r"(r[2]), "=r"(r[3]) : "r"(a));
}

__device__ __forceinline__ void cp16(__half* smem, const __half* gmem) {
    uint32_t s = (uint32_t)__cvta_generic_to_shared(smem);
    asm volatile("cp.async.cg.shared.global [%0], [%1], 16;\n" :: "r"(s), "l"(gmem));
}
__device__ __forceinline__ void cp_commit() { asm volatile("cp.async.commit_group;\n"); }
template<int N>
__device__ __forceinline__ void cp_wait() { asm volatile("cp.async.wait_group %0;\n" :: "n"(N)); }

// ---------------- GEMM ----------------
// C[M,N] = A[M,K] @ B^T + epi; A fp16 [M][K], B fp16 [N][K] k-major.
//   CAUSAL : skip CTA if N-tile fully above diagonal (square 128 tiles)
//   PVT    : truncate K loop at end of this M-tile (P@V causal structure)
#define EPI_STORE_F    0   /* fp32 store */
#define EPI_BIAS_H     1   /* q,k: bias, fp16 store */
#define EPI_BIAS_RES_F 2   /* xmid/out: bias+residual, fp32 store */
#define EPI_GELU_H     3   /* h1: gelu(bias), fp16 store */
#define EPI_VT_H       4   /* v: bias, fp16 store transposed as V^T */
#define EPI_STORE_H    5   /* fp16 store */
#define EPI_EXP_H      6   /* scores: exp + row partial sums (Cf=psum), fp16 E store */
#define EPI_DIV_H      7   /* attn: divide by rowsum (res=psum), fp16 store */

template<int EPI, bool CAUSAL, bool PVT>
__global__ void __launch_bounds__(CTHREADS, 2)
gemm_k(const __half* __restrict__ A, const __half* __restrict__ B,
       const float* __restrict__ bias, const float* __restrict__ res,
       float* __restrict__ Cf, __half* __restrict__ Ch,
       int M, int N, int K,
       long long aB, long long bB, long long cB)
{
    const int bn = blockIdx.x, bm = blockIdx.y, bz = blockIdx.z;
    if (CAUSAL && bn > bm) return;
    A += (long long)bz * aB;
    B += (long long)bz * bB;

    extern __shared__ __half sm[];

    const int tid  = threadIdx.x;
    const int lane = tid & 31;
    const int warp = tid >> 5;
    const int wm = (warp >> 1) * 64;   // 2 warps along M (64 rows each)
    const int wn = (warp & 1) * 64;    // 2 warps along N (64 cols each)
    const int g  = lane >> 2;
    const int tg = lane & 3;
    const int m0 = bm * MT, n0 = bn * NT;

    int ktiles = K / KT;
    if (PVT) { int kt2 = (bm + 1) * (MT / KT); if (kt2 < ktiles) ktiles = kt2; }

    float acc[4][8][4];
#pragma unroll
    for (int i = 0; i < 4; i++)
#pragma unroll
        for (int j = 0; j < 8; j++)
#pragma unroll
            for (int r = 0; r < 4; r++) acc[i][j][r] = 0.0f;

    // ldmatrix per-lane selectors (halves)
    const int l8 = lane & 7, q = lane >> 3;
    const int a_row = (q & 1) * 8 + l8;
    const int a_col = (q >> 1) * 8;
    const int b_row = (q >> 1) * 8 + l8;
    const int b_col = (q & 1) * 8;

    auto issue = [&](int stage, int kt) {
        __half* sA = sm + stage * STAGE_H;
        __half* sB = sA + A_STAGE;
#pragma unroll
        for (int i = 0; i < 8; i++) {             // A: 128 rows x 8 chunks of 16B
            const int idx = tid + i * CTHREADS;
            const int row = idx >> 3, ch = idx & 7;
            cp16(&sA[row * ASTRIDE + ch * 8],
                 A + (size_t)(m0 + row) * K + kt * KT + ch * 8);
        }
#pragma unroll
        for (int i = 0; i < 8; i++) {             // B: 128 n-rows x 8 chunks
            const int idx = tid + i * CTHREADS;
            const int row = idx >> 3, ch = idx & 7;
            cp16(&sB[row * BSTRIDE + ch * 8],
                 B + (size_t)(n0 + row) * K + kt * KT + ch * 8);
        }
    };

#pragma unroll
    for (int s = 0; s < STAGES - 1; s++) {
        if (s < ktiles) issue(s, s);
        cp_commit();
    }

    uint32_t af[2][4][4];
    uint32_t bf[2][8][2];

    for (int kt = 0; kt < ktiles; kt++) {
        cp_wait<STAGES - 2>();
        __syncthreads();

        const int nkt = kt + STAGES - 1;
        if (nkt < ktiles) issue(nkt % STAGES, nkt);
        cp_commit();

        const __half* sA = sm + (kt % STAGES) * STAGE_H;
        const __half* sB = sA + A_STAGE;

        auto ldfrag = [&](int buf, int ks) {
            const int k0 = ks * 16;
#pragma unroll
            for (int mi = 0; mi < 4; mi++)
                ldm4(af[buf][mi], &sA[(wm + mi * 16 + a_row) * ASTRIDE + k0 + a_col]);
#pragma unroll
            for (int np = 0; np < 4; np++) {
                uint32_t r[4];
                ldm4(r, &sB[(wn + np * 16 + b_row) * BSTRIDE + k0 + b_col]);
                bf[buf][2*np][0] = r[0]; bf[buf][2*np][1] = r[1];
                bf[buf][2*np+1][0] = r[2]; bf[buf][2*np+1][1] = r[3];
            }
        };

        ldfrag(0, 0);
#pragma unroll
        for (int ks = 0; ks < 4; ks++) {          // 4 k-steps of 16, double-buffered
            if (ks < 3) ldfrag((ks + 1) & 1, ks + 1);
            const int cb = ks & 1;
#pragma unroll
            for (int mi = 0; mi < 4; mi++)
#pragma unroll
                for (int ni = 0; ni < 8; ni++)
                    mma_f16(acc[mi][ni], af[cb][mi], bf[cb][ni]);
        }
    }
    __syncthreads();

    // ---- special epilogue preambles ----
    if (EPI == EPI_EXP_H) {
        // exp-transform acc in place, compute per-row partial sums -> psum (Cf)
        const bool diag = (bn == bm);
        float* ps = (float*)sm;   // [128 rows][2 warp-halves]
#pragma unroll
        for (int mi = 0; mi < 4; mi++) {
#pragma unroll
            for (int h = 0; h < 2; h++) {
                const int rl = wm + mi * 16 + g + h * 8;
                const int rr = m0 + rl;
                float s8 = 0.0f;
#pragma unroll
                for (int ni = 0; ni < 8; ni++) {
#pragma unroll
                    for (int e2 = 0; e2 < 2; e2++) {
                        const int c = n0 + wn + ni * 8 + tg * 2 + e2;
                        float v = acc[mi][ni][h * 2 + e2];
                        float ev = (diag && c > rr) ? 0.0f
                                 : ex2a(fmaf(v, K1EXP, -K2EXP));
                        acc[mi][ni][h * 2 + e2] = ev;
                        s8 += ev;
                    }
                }
                s8 += __shfl_xor_sync(0xffffffffu, s8, 1);
                s8 += __shfl_xor_sync(0xffffffffu, s8, 2);
                if (tg == 0) ps[rl * 2 + (warp & 1)] = s8;
            }
        }
        __syncthreads();
        if (tid < MT)
            Cf[((size_t)bz * NTILES_S + bn) * SEQ + m0 + tid] = ps[tid * 2] + ps[tid * 2 + 1];
    }

    float* rs = (float*)sm;       // rowscale for EPI_DIV_H
    if (EPI == EPI_DIV_H) {
        if (tid < MT) {
            const float* pp = res + (size_t)bz * NTILES_S * SEQ + m0 + tid;
            float s = 0.0f;
            for (int j = 0; j <= bm; j++) s += pp[(size_t)j * SEQ];
            rs[tid] = 1.0f / s;
        }
        __syncthreads();
    }

    // ---- stores ----
    if (EPI != EPI_VT_H) {
#pragma unroll
        for (int mi = 0; mi < 4; mi++) {
#pragma unroll
            for (int ni = 0; ni < 8; ni++) {
                const int rl = wm + mi * 16 + g;
                const int c = n0 + wn + ni * 8 + tg * 2;
#pragma unroll
                for (int h = 0; h < 2; h++) {
                    const int rr = m0 + rl + h * 8;
                    float v0 = acc[mi][ni][h * 2 + 0];
                    float v1 = acc[mi][ni][h * 2 + 1];
                    if (EPI == EPI_BIAS_H || EPI == EPI_BIAS_RES_F || EPI == EPI_GELU_H) {
                        v0 += bias[c]; v1 += bias[c + 1];
                    }
                    if (EPI == EPI_BIAS_RES_F) {
                        v0 += res[(size_t)rr * N + c];
                        v1 += res[(size_t)rr * N + c + 1];
                    }
                    if (EPI == EPI_GELU_H) { v0 = gelu_exact(v0); v1 = gelu_exact(v1); }
                    if (EPI == EPI_DIV_H) {
                        const float sc_ = rs[rl + h * 8];
                        v0 *= sc_; v1 *= sc_;
                    }
                    const size_t o = (size_t)bz * cB + (size_t)rr * N + c;
                    if (EPI == EPI_STORE_F || EPI == EPI_BIAS_RES_F) {
                        *(float2*)&Cf[o] = make_float2(v0, v1);
                    } else {
                        *(__half2*)&Ch[o] = __floats2half2_rn(v0, v1);
                    }
                }
            }
        }
    } else {
        // stage fp16 C tile transposed in smem as [n][m], then write V^T coalesced
        __half* stg = sm;
#pragma unroll
        for (int mi = 0; mi < 4; mi++) {
#pragma unroll
            for (int ni = 0; ni < 8; ni++) {
                const int c = wn + ni * 8 + tg * 2;
                const float b0 = bias[n0 + c], b1 = bias[n0 + c + 1];
#pragma unroll
                for (int h = 0; h < 2; h++) {
                    const int r = wm + mi * 16 + g + h * 8;
                    stg[(c    ) * VT_STRIDE + r] = __float2half_rn(acc[mi][ni][h * 2 + 0] + b0);
                    stg[(c + 1) * VT_STRIDE + r] = __float2half_rn(acc[mi][ni][h * 2 + 1] + b1);
                }
            }
        }
        __syncthreads();
        const int b = m0 >> 11, t0 = m0 & 2047;
        for (int nr = warp * 32; nr < warp * 32 + 32; nr++) {
            const int n = n0 + nr;
            __half* dst = Ch + ((size_t)b * DIM + n) * SEQ + t0;
            const int m = lane * 4;
            *(uint2*)&dst[m] = *(uint2*)&stg[nr * VT_STRIDE + m];
        }
    }
}

// ---------------- weight transpose+convert: w[K][N] fp32 -> wt[N][K] fp16 ----------------
__global__ void wtrans_k(const float* __restrict__ w, __half* __restrict__ wt, int Kd, int Nd)
{
    __shared__ float t[32][33];
    const int bx = blockIdx.x, by = blockIdx.y;
    const int tx = threadIdx.x, ty = threadIdx.y;   // (32,8)
#pragma unroll
    for (int j = 0; j < 4; j++)
        t[ty + j * 8][tx] = w[(size_t)(by * 32 + ty + j * 8) * Nd + bx * 32 + tx];
    __syncthreads();
#pragma unroll
    for (int j = 0; j < 4; j++)
        wt[(size_t)(bx * 32 + ty + j * 8) * Kd + by * 32 + tx] = __float2half_rn(t[tx][ty + j * 8]);
}

// ---------------- RMSNorm: fp32 in -> fp16 out ----------------
__global__ void __launch_bounds__(256, 1)
rmsnorm_k(const float* __restrict__ x, const float* __restrict__ w, __half* __restrict__ o)
{
    __shared__ float red[8];
    __shared__ float bc;
    const int row = blockIdx.x;
    const size_t base = (size_t)row * DIM;
    const int tid = threadIdx.x, lane = tid & 31, warp = tid >> 5;

    float4 xv = ((const float4*)(x + base))[tid];
    float ss = xv.x * xv.x + xv.y * xv.y + xv.z * xv.z + xv.w * xv.w;
#pragma unroll
    for (int off = 16; off; off >>= 1) ss += __shfl_xor_sync(0xffffffffu, ss, off);
    if (lane == 0) red[warp] = ss;
    __syncthreads();
    if (tid == 0) {
        float t = 0.0f;
#pragma unroll
        for (int i = 0; i < 8; i++) t += red[i];
        bc = rsqrtf(t * (1.0f / DIM) + 1e-6f);
    }
    __syncthreads();
    const float inv = bc;
    float4 wv = ((const float4*)w)[tid];
    __half2 h0 = __floats2half2_rn(xv.x * inv * wv.x, xv.y * inv * wv.y);
    __half2 h1 = __floats2half2_rn(xv.z * inv * wv.z, xv.w * inv * wv.w);
    *(__half2*)&o[base + tid * 4 + 0] = h0;
    *(__half2*)&o[base + tid * 4 + 2] = h1;
}

// ---------------- launch ----------------
extern "C" void kernel_launch(void* const* d_in, const int* in_sizes, int n_in,
                              void* d_out, int out_size)
{
    (void)in_sizes; (void)n_in; (void)out_size;
    const float* x   = (const float*)d_in[0];
    const float* anw = (const float*)d_in[1];
    const float* mnw = (const float*)d_in[2];
    const float* wq  = (const float*)d_in[3];
    const float* bq  = (const float*)d_in[4];
    const float* wk  = (const float*)d_in[5];
    const float* bk  = (const float*)d_in[6];
    const float* wv  = (const float*)d_in[7];
    const float* bv  = (const float*)d_in[8];
    const float* wo  = (const float*)d_in[9];
    const float* bo  = (const float*)d_in[10];
    const float* w1  = (const float*)d_in[11];
    const float* b1  = (const float*)d_in[12];
    const float* w2  = (const float*)d_in[13];
    const float* b2  = (const float*)d_in[14];
    float* out = (float*)d_out;

    __half *xn, *q, *k, *vt, *attn, *h1, *e;
    __half *wqt, *wkt, *wvt, *wot, *w1t, *w2t;
    float *psum, *xmid;
    cudaGetSymbolAddress((void**)&xn,   g_xn);
    cudaGetSymbolAddress((void**)&q,    g_q);
    cudaGetSymbolAddress((void**)&k,    g_k);
    cudaGetSymbolAddress((void**)&vt,   g_vt);
    cudaGetSymbolAddress((void**)&attn, g_attn);
    cudaGetSymbolAddress((void**)&h1,   g_h1);
    cudaGetSymbolAddress((void**)&e,    g_e);
    cudaGetSymbolAddress((void**)&psum, g_psum);
    cudaGetSymbolAddress((void**)&xmid, g_xmid);
    cudaGetSymbolAddress((void**)&wqt,  g_wqt);
    cudaGetSymbolAddress((void**)&wkt,  g_wkt);
    cudaGetSymbolAddress((void**)&wvt,  g_wvt);
    cudaGetSymbolAddress((void**)&wot,  g_wot);
    cudaGetSymbolAddress((void**)&w1t,  g_w1t);
    cudaGetSymbolAddress((void**)&w2t,  g_w2t);

    cudaFuncSetAttribute(gemm_k<EPI_BIAS_H,     false, false>,
                         cudaFuncAttributeMaxDynamicSharedMemorySize, SMEM_BYTES);
    cudaFuncSetAttribute(gemm_k<EPI_VT_H,       false, false>,
                         cudaFuncAttributeMaxDynamicSharedMemorySize, SMEM_BYTES);
    cudaFuncSetAttribute(gemm_k<EPI_EXP_H,      true,  false>,
                         cudaFuncAttributeMaxDynamicSharedMemorySize, SMEM_BYTES);
    cudaFuncSetAttribute(gemm_k<EPI_DIV_H,      false, true >,
                         cudaFuncAttributeMaxDynamicSharedMemorySize, SMEM_BYTES);
    cudaFuncSetAttribute(gemm_k<EPI_BIAS_RES_F, false, false>,
                         cudaFuncAttributeMaxDynamicSharedMemorySize, SMEM_BYTES);
    cudaFuncSetAttribute(gemm_k<EPI_GELU_H,     false, false>,
                         cudaFuncAttributeMaxDynamicSharedMemorySize, SMEM_BYTES);

    const long long SD = (long long)SEQ * DIM;
    const long long SS = (long long)SEQ * SEQ;
    const dim3 wb(32, 8);

    // 0) transpose+convert weights to fp16 [N][K]
    wtrans_k<<<dim3(DIM/32, DIM/32), wb>>>(wq, wqt, DIM, DIM);
    wtrans_k<<<dim3(DIM/32, DIM/32), wb>>>(wk, wkt, DIM, DIM);
    wtrans_k<<<dim3(DIM/32, DIM/32), wb>>>(wv, wvt, DIM, DIM);
    wtrans_k<<<dim3(DIM/32, DIM/32), wb>>>(wo, wot, DIM, DIM);
    wtrans_k<<<dim3(HID/32, DIM/32), wb>>>(w1, w1t, DIM, HID);
    wtrans_k<<<dim3(DIM/32, HID/32), wb>>>(w2, w2t, HID, DIM);

    // 1) xn = rmsnorm(x) * attn_norm_w  (fp16)
    rmsnorm_k<<<ROWS, 256>>>(x, anw, xn);

    // 2) Q, K fp16; V written transposed as V^T fp16
    gemm_k<EPI_BIAS_H, false, false><<<dim3(DIM/NT, ROWS/MT, 1), CTHREADS, SMEM_BYTES>>>(
        xn, wqt, bq, nullptr, nullptr, q, ROWS, DIM, DIM, 0, 0, 0);
    gemm_k<EPI_BIAS_H, false, false><<<dim3(DIM/NT, ROWS/MT, 1), CTHREADS, SMEM_BYTES>>>(
        xn, wkt, bk, nullptr, nullptr, k, ROWS, DIM, DIM, 0, 0, 0);
    gemm_k<EPI_VT_H, false, false><<<dim3(DIM/NT, ROWS/MT, 1), CTHREADS, SMEM_BYTES>>>(
        xn, wvt, bv, nullptr, nullptr, vt, ROWS, DIM, DIM, 0, 0, 0);

    // 3) E = exp(QK^T/32 - 4) fp16 + per-tile row sums (causal block-skip, in-tile mask)
    gemm_k<EPI_EXP_H, true, false><<<dim3(SEQ/NT, SEQ/MT, BATCH), CTHREADS, SMEM_BYTES>>>(
        q, k, nullptr, nullptr, psum, e, SEQ, SEQ, DIM, SD, SD, SS);

    // 4) attn = (E @ V) / rowsum  (B = V^T [d][s], K loop truncated)
    gemm_k<EPI_DIV_H, false, true><<<dim3(DIM/NT, SEQ/MT, BATCH), CTHREADS, SMEM_BYTES>>>(
        e, vt, nullptr, psum, nullptr, attn, SEQ, DIM, SEQ, SS, SD, SD);

    // 5) xmid = x + attn @ wo + bo  (fp32)
    gemm_k<EPI_BIAS_RES_F, false, false><<<dim3(DIM/NT, ROWS/MT, 1), CTHREADS, SMEM_BYTES>>>(
        attn, wot, bo, x, xmid, nullptr, ROWS, DIM, DIM, 0, 0, 0);

    // 6) h = rmsnorm(xmid) * mlp_norm_w  (fp16)
    rmsnorm_k<<<ROWS, 256>>>(xmid, mnw, xn);

    // 7) h1 = gelu(h @ w1 + b1)  (fp16)
    gemm_k<EPI_GELU_H, false, false><<<dim3(HID/NT, ROWS/MT, 1), CTHREADS, SMEM_BYTES>>>(
        xn, w1t, b1, nullptr, nullptr, h1, ROWS, HID, DIM, 0, 0, 0);

    // 8) out = xmid + h1 @ w2 + b2  (fp32)
    gemm_k<EPI_BIAS_RES_F, false, false><<<dim3(DIM/NT, ROWS/MT, 1), CTHREADS, SMEM_BYTES>>>(
        h1, w2t, b2, xmid, out, nullptr, ROWS, DIM, HID, 0, 0, 0);
}